// round 12
// baseline (speedup 1.0000x reference)
#include <cuda_runtime.h>
#include <cuda_bf16.h>
#include <cstdint>

#define SEQ 2048
#define DIM 4096
#define NH 32
#define NKV 8
#define HD 128
#define KVD 1024   // NKV*HD
#define NQKV 6144  // DIM + 2*KVD

// ---------------- scratch (device globals) ----------------
__device__ __align__(128) __nv_bfloat16 g_xh[SEQ * DIM];
__device__ __align__(128) __nv_bfloat16 g_xl[SEQ * DIM];
__device__ __align__(128) __nv_bfloat16 g_ah[SEQ * DIM];
__device__ __align__(128) __nv_bfloat16 g_al[SEQ * DIM];
__device__ __align__(128) __nv_bfloat16 g_qh[SEQ * DIM];
__device__ __align__(128) __nv_bfloat16 g_ql[SEQ * DIM];
__device__ __align__(128) __nv_bfloat16 g_kh[SEQ * KVD];
__device__ __align__(128) __nv_bfloat16 g_kl[SEQ * KVD];
__device__ __align__(128) __nv_bfloat16 g_vh[SEQ * KVD];
__device__ __align__(128) __nv_bfloat16 g_vl[SEQ * KVD];
__device__ __align__(128) __nv_bfloat16 g_wh[NQKV * DIM];
__device__ __align__(128) __nv_bfloat16 g_wl[NQKV * DIM];
__device__ __align__(128) __nv_bfloat16 g_woh[DIM * DIM];
__device__ __align__(128) __nv_bfloat16 g_wol[DIM * DIM];

// ---------------- PTX helpers (baseline-PTX, sm_80-class) ----------------
__device__ __forceinline__ uint32_t smem_u32(const void* p) {
    uint32_t a;
    asm("{ .reg .u64 t; cvta.to.shared.u64 t, %1; cvt.u32.u64 %0, t; }" : "=r"(a) : "l"(p));
    return a;
}
__device__ __forceinline__ void cpa16(uint32_t s, const void* g) {
    asm volatile("cp.async.cg.shared.global [%0], [%1], 16;" :: "r"(s), "l"(g));
}
__device__ __forceinline__ void ldsm4(unsigned* r, uint32_t addr) {
    asm volatile("ldmatrix.sync.aligned.m8n8.x4.shared.b16 {%0,%1,%2,%3}, [%4];"
                 : "=r"(r[0]), "=r"(r[1]), "=r"(r[2]), "=r"(r[3]) : "r"(addr));
}
__device__ __forceinline__ void ldsm2(unsigned* r, uint32_t addr) {
    asm volatile("ldmatrix.sync.aligned.m8n8.x2.shared.b16 {%0,%1}, [%2];"
                 : "=r"(r[0]), "=r"(r[1]) : "r"(addr));
}
__device__ __forceinline__ void ldsm2t(unsigned* r, uint32_t addr) {
    asm volatile("ldmatrix.sync.aligned.m8n8.x2.trans.shared.b16 {%0,%1}, [%2];"
                 : "=r"(r[0]), "=r"(r[1]) : "r"(addr));
}
__device__ __forceinline__ void mma16816(float* d, const unsigned* a, const unsigned* b) {
    asm volatile(
        "mma.sync.aligned.m16n8k16.row.col.f32.bf16.bf16.f32 "
        "{%0,%1,%2,%3}, {%4,%5,%6,%7}, {%8,%9}, {%0,%1,%2,%3};"
        : "+f"(d[0]), "+f"(d[1]), "+f"(d[2]), "+f"(d[3])
        : "r"(a[0]), "r"(a[1]), "r"(a[2]), "r"(a[3]), "r"(b[0]), "r"(b[1]));
}
__device__ __forceinline__ unsigned pack_bf2(float lo, float hi) {
    unsigned d;
    asm("cvt.rn.bf16x2.f32 %0, %1, %2;" : "=r"(d) : "f"(hi), "f"(lo));
    return d;
}
__device__ __forceinline__ float bf2lo(unsigned r) { return __uint_as_float(r << 16); }
__device__ __forceinline__ float bf2hi(unsigned r) { return __uint_as_float(r & 0xffff0000u); }

// ---------------- conversion kernels ----------------
__global__ void split_kernel(const float* __restrict__ x, __nv_bfloat16* __restrict__ h,
                             __nv_bfloat16* __restrict__ l, int n) {
    int i = blockIdx.x * blockDim.x + threadIdx.x;
    if (i >= n) return;
    float v = x[i];
    __nv_bfloat16 hi = __float2bfloat16(v);
    __nv_bfloat16 lo = __float2bfloat16(v - __bfloat162float(hi));
    h[i] = hi;
    l[i] = lo;
}

__global__ void transpose_split_qkv(const float* __restrict__ wq, const float* __restrict__ wk,
                                    const float* __restrict__ wv,
                                    __nv_bfloat16* __restrict__ th, __nv_bfloat16* __restrict__ tl) {
    __shared__ float tile[32][33];
    int k0 = blockIdx.y * 32, n0 = blockIdx.x * 32;
    int tx = threadIdx.x, ty = threadIdx.y;   // 32 x 8
    const float* src;
    int nn0, ldn;
    if (n0 < DIM) { src = wq; nn0 = n0; ldn = DIM; }
    else if (n0 < DIM + KVD) { src = wk; nn0 = n0 - DIM; ldn = KVD; }
    else { src = wv; nn0 = n0 - DIM - KVD; ldn = KVD; }
#pragma unroll
    for (int r = 0; r < 4; r++)
        tile[ty + r * 8][tx] = src[(size_t)(k0 + ty + r * 8) * ldn + nn0 + tx];
    __syncthreads();
#pragma unroll
    for (int r = 0; r < 4; r++) {
        float v = tile[tx][ty + r * 8];
        __nv_bfloat16 hi = __float2bfloat16(v);
        __nv_bfloat16 lo = __float2bfloat16(v - __bfloat162float(hi));
        size_t o = (size_t)(n0 + ty + r * 8) * DIM + k0 + tx;
        th[o] = hi;
        tl[o] = lo;
    }
}

__global__ void transpose_split(const float* __restrict__ w, __nv_bfloat16* __restrict__ th,
                                __nv_bfloat16* __restrict__ tl, int K, int N) {
    __shared__ float tile[32][33];
    int k0 = blockIdx.y * 32, n0 = blockIdx.x * 32;
    int tx = threadIdx.x, ty = threadIdx.y;
#pragma unroll
    for (int r = 0; r < 4; r++)
        tile[ty + r * 8][tx] = w[(size_t)(k0 + ty + r * 8) * N + n0 + tx];
    __syncthreads();
#pragma unroll
    for (int r = 0; r < 4; r++) {
        float v = tile[tx][ty + r * 8];
        __nv_bfloat16 hi = __float2bfloat16(v);
        __nv_bfloat16 lo = __float2bfloat16(v - __bfloat162float(hi));
        size_t o = (size_t)(n0 + ty + r * 8) * K + k0 + tx;
        th[o] = hi;
        tl[o] = lo;
    }
}

// ---------------- HMMA bf16x3 GEMM (R10 mainloop; PERSISTENT tile loop) ----------
// CTA 128x128, 4 warps (2m x 2n), warp tile 64x64, BK=32, 2-stage cp.async
// with wait_group 1 overlap (R10-proven). Grid = 296 persistent CTAs.
// MODE 0: C fp32 out. MODE 1: fused RoPE + bf16 hi/lo split QKV epilogue.
#define BM 128
#define BN 128
#define BK 32
#define LDE 40                     // padded bf16/row (80B: conflict-free LDSM)
#define ARR (128 * LDE * 2)        // 10240 B
#define STG (4 * ARR)              // 40960 B per stage
#define SMEM_GEMM (2 * STG)        // 81920 B
#define PERSIST 296                // 148 SMs x 2 CTAs

template <int MODE>
__global__ __launch_bounds__(128, 2)
void gemm_hmma(const __nv_bfloat16* __restrict__ Ah, const __nv_bfloat16* __restrict__ Al,
               const __nv_bfloat16* __restrict__ Bh, const __nv_bfloat16* __restrict__ Bl,
               float* __restrict__ C,
               const float* __restrict__ cs, const float* __restrict__ sn,
               __nv_bfloat16* __restrict__ qh, __nv_bfloat16* __restrict__ ql,
               __nv_bfloat16* __restrict__ kh, __nv_bfloat16* __restrict__ kl,
               __nv_bfloat16* __restrict__ vh, __nv_bfloat16* __restrict__ vl,
               int M, int N, int K) {
    extern __shared__ char smem[];
    const uint32_t sb = smem_u32(smem);
    const int tid = threadIdx.x;
    const int lane = tid & 31, warp = tid >> 5;
    const int wm = (warp & 1) * 64, wn = (warp >> 1) * 64;

    const int tn = N / BN;
    const int ntiles = (M / BM) * tn;

#pragma unroll 1
    for (int tile = blockIdx.x; tile < ntiles; tile += gridDim.x) {
        const int m0 = (tile / tn) * BM, n0 = (tile % tn) * BN;

        float acc[4][8][4];
#pragma unroll
        for (int m = 0; m < 4; m++)
#pragma unroll
            for (int j = 0; j < 8; j++)
#pragma unroll
                for (int v = 0; v < 4; v++) acc[m][j][v] = 0.f;

        auto load_stage = [&](int buf, int ko) {
            uint32_t s0 = sb + buf * STG;
#pragma unroll
            for (int s = tid; s < 512; s += 128) {
                int row = s >> 2, c = s & 3;
                uint32_t so = s0 + (uint32_t)row * (LDE * 2) + c * 16;
                size_t go = (size_t)row * K + ko + c * 8;
                cpa16(so, Ah + (size_t)m0 * K + go);
                cpa16(so + ARR, Al + (size_t)m0 * K + go);
                cpa16(so + 2 * ARR, Bh + (size_t)n0 * K + go);
                cpa16(so + 3 * ARR, Bl + (size_t)n0 * K + go);
            }
            asm volatile("cp.async.commit_group;");
        };

        load_stage(0, 0);
        const int NS = K / BK;
#pragma unroll 1
        for (int s = 0; s < NS; s++) {
            if (s + 1 < NS) {
                load_stage((s + 1) & 1, (s + 1) * BK);
                asm volatile("cp.async.wait_group 1;");
            } else {
                asm volatile("cp.async.wait_group 0;");
            }
            __syncthreads();

            const uint32_t base = sb + (s & 1) * STG;
#pragma unroll
            for (int ks = 0; ks < 2; ks++) {
                const int k0 = ks * 16;
                unsigned ah[4][4], al[4][4];
#pragma unroll
                for (int m = 0; m < 4; m++) {
                    uint32_t aa = base +
                        (uint32_t)(wm + m * 16 + (lane & 15)) * (LDE * 2) +
                        (uint32_t)(k0 + (lane >> 4) * 8) * 2;
                    ldsm4(ah[m], aa);
                    ldsm4(al[m], aa + ARR);
                }
#pragma unroll
                for (int j = 0; j < 8; j++) {
                    uint32_t ba = base + 2 * ARR +
                        (uint32_t)(wn + j * 8 + (lane & 7)) * (LDE * 2) +
                        (uint32_t)(k0 + ((lane >> 3) & 1) * 8) * 2;
                    unsigned bh[2], bl[2];
                    ldsm2(bh, ba);
                    ldsm2(bl, ba + ARR);
#pragma unroll
                    for (int m = 0; m < 4; m++) {
                        mma16816(acc[m][j], ah[m], bh);
                        mma16816(acc[m][j], ah[m], bl);
                        mma16816(acc[m][j], al[m], bh);
                    }
                }
            }
            __syncthreads();
        }

        if (MODE == 0) {
#pragma unroll
            for (int m = 0; m < 4; m++) {
                int r0 = m0 + wm + m * 16 + (lane >> 2);
#pragma unroll
                for (int j = 0; j < 8; j++) {
                    int c = n0 + wn + j * 8 + (lane & 3) * 2;
                    *(float2*)(C + (size_t)r0 * N + c) =
                        make_float2(acc[m][j][0], acc[m][j][1]);
                    *(float2*)(C + (size_t)(r0 + 8) * N + c) =
                        make_float2(acc[m][j][2], acc[m][j][3]);
                }
            }
        } else {
            // fused RoPE + bf16 hi/lo split; CTA's n-range lies entirely in Q, K, or V.
            __nv_bfloat16 *oh, *ol;
            int ld, nbase;
            bool rope;
            if (n0 < DIM) { oh = qh; ol = ql; ld = DIM; nbase = 0; rope = true; }
            else if (n0 < DIM + KVD) { oh = kh; ol = kl; ld = KVD; nbase = DIM; rope = true; }
            else { oh = vh; ol = vl; ld = KVD; nbase = DIM + KVD; rope = false; }
#pragma unroll
            for (int m = 0; m < 4; m++) {
                int r0 = m0 + wm + m * 16 + (lane >> 2);
#pragma unroll
                for (int j = 0; j < 8; j++) {
                    int c = n0 + wn + j * 8 + (lane & 3) * 2;
                    float a0 = acc[m][j][0], a1 = acc[m][j][1];   // row r0
                    float b0 = acc[m][j][2], b1 = acc[m][j][3];   // row r0+8
                    if (rope) {
                        int i = (c & 127) >> 1;
                        float c0 = cs[r0 * 64 + i], s0 = sn[r0 * 64 + i];
                        float c1 = cs[(r0 + 8) * 64 + i], s1 = sn[(r0 + 8) * 64 + i];
                        float t0 = a0 * c0 - a1 * s0, t1 = a0 * s0 + a1 * c0;
                        a0 = t0; a1 = t1;
                        t0 = b0 * c1 - b1 * s1; t1 = b0 * s1 + b1 * c1;
                        b0 = t0; b1 = t1;
                    }
                    int cl = c - nbase;
                    unsigned hA = pack_bf2(a0, a1);
                    unsigned lA = pack_bf2(a0 - bf2lo(hA), a1 - bf2hi(hA));
                    unsigned hB = pack_bf2(b0, b1);
                    unsigned lB = pack_bf2(b0 - bf2lo(hB), b1 - bf2hi(hB));
                    *(unsigned*)(oh + (size_t)r0 * ld + cl) = hA;
                    *(unsigned*)(ol + (size_t)r0 * ld + cl) = lA;
                    *(unsigned*)(oh + (size_t)(r0 + 8) * ld + cl) = hB;
                    *(unsigned*)(ol + (size_t)(r0 + 8) * ld + cl) = lB;
                }
            }
        }
        // mainloop's final __syncthreads already ordered all smem reads before here;
        // epilogue touches only registers/global, so next tile's loads are safe.
    }
}

// ---------------- tensorized flash attention (R10 structure) ----------------
#define AQ 128
#define AKV 64
#define LDA 136
#define QARR (128 * LDA * 2)
#define KARR (64 * LDA * 2)
#define KVSTG (4 * KARR)
#define SMEM_ATT (2 * QARR + 2 * KVSTG)   // 208896 B

__global__ __launch_bounds__(256, 1)
void attn_mma(const __nv_bfloat16* __restrict__ Qh, const __nv_bfloat16* __restrict__ Ql,
              const __nv_bfloat16* __restrict__ Kh, const __nv_bfloat16* __restrict__ Kl,
              const __nv_bfloat16* __restrict__ Vh, const __nv_bfloat16* __restrict__ Vl,
              __nv_bfloat16* __restrict__ Oh, __nv_bfloat16* __restrict__ Ol) {
    extern __shared__ char smem[];
    const uint32_t sb = smem_u32(smem);
    const int tid = threadIdx.x;
    const int lane = tid & 31, warp = tid >> 5;
    const int h = blockIdx.y;
    const int qt = (gridDim.x - 1) - blockIdx.x;
    const int q0 = qt * AQ;
    const int kvh = h >> 2;
    const float scale = 0.08838834764831845f;
    const float NEGF = -1e30f;

#pragma unroll
    for (int s = tid; s < 128 * 16; s += 256) {
        int row = s >> 4, c = s & 15;
        uint32_t so = sb + (uint32_t)row * (LDA * 2) + c * 16;
        size_t go = (size_t)(q0 + row) * DIM + h * HD + c * 8;
        cpa16(so, Qh + go);
        cpa16(so + QARR, Ql + go);
    }
    auto load_kv = [&](int buf, int k0) {
        uint32_t b0 = sb + 2 * QARR + buf * KVSTG;
#pragma unroll
        for (int s = tid; s < 1024; s += 256) {
            int row = s >> 4, c = s & 15;
            uint32_t so = b0 + (uint32_t)row * (LDA * 2) + c * 16;
            size_t go = (size_t)(k0 + row) * KVD + kvh * HD + c * 8;
            cpa16(so, Kh + go);
            cpa16(so + KARR, Kl + go);
            cpa16(so + 2 * KARR, Vh + go);
            cpa16(so + 3 * KARR, Vl + go);
        }
        asm volatile("cp.async.commit_group;");
    };
    load_kv(0, 0);

    const int rA = q0 + warp * 16 + (lane >> 2);
    const int qwmax = q0 + warp * 16 + 15;
    float mA = NEGF, mB = NEGF, lA = 0.f, lB = 0.f;
    float o[16][4];
#pragma unroll
    for (int j = 0; j < 16; j++)
#pragma unroll
        for (int v = 0; v < 4; v++) o[j][v] = 0.f;

    const int ntiles = (q0 + AQ) / AKV;
#pragma unroll 1
    for (int t = 0; t < ntiles; t++) {
        const int k0 = t * AKV;
        if (t + 1 < ntiles) {
            load_kv((t + 1) & 1, (t + 1) * AKV);
            asm volatile("cp.async.wait_group 1;");
        } else {
            asm volatile("cp.async.wait_group 0;");
        }
        __syncthreads();

        if (k0 <= qwmax) {
            const uint32_t kb = sb + 2 * QARR + (t & 1) * KVSTG;
            const uint32_t vb = kb + 2 * KARR;

            float s[8][4];
#pragma unroll
            for (int j = 0; j < 8; j++)
#pragma unroll
                for (int v = 0; v < 4; v++) s[j][v] = 0.f;

#pragma unroll
            for (int kc = 0; kc < 8; kc++) {
                uint32_t qa = sb + (uint32_t)(warp * 16 + (lane & 15)) * (LDA * 2) +
                              (uint32_t)(kc * 16 + (lane >> 4) * 8) * 2;
                unsigned aqh[4], aql[4];
                ldsm4(aqh, qa);
                ldsm4(aql, qa + QARR);
#pragma unroll
                for (int j = 0; j < 8; j++) {
                    uint32_t ka = kb + (uint32_t)(j * 8 + (lane & 7)) * (LDA * 2) +
                                  (uint32_t)(kc * 16 + ((lane >> 3) & 1) * 8) * 2;
                    unsigned bkh[2], bkl[2];
                    ldsm2(bkh, ka);
                    ldsm2(bkl, ka + KARR);
                    mma16816(s[j], aqh, bkh);
                    mma16816(s[j], aqh, bkl);
                    mma16816(s[j], aql, bkh);
                }
            }

            const bool need_mask = (k0 + AKV - 1) > (q0 + warp * 16);
#pragma unroll
            for (int j = 0; j < 8; j++) {
#pragma unroll
                for (int v = 0; v < 4; v++) s[j][v] *= scale;
                if (need_mask) {
                    int cg = k0 + j * 8 + (lane & 3) * 2;
                    if (cg > rA) s[j][0] = NEGF;
                    if (cg + 1 > rA) s[j][1] = NEGF;
                    if (cg > rA + 8) s[j][2] = NEGF;
                    if (cg + 1 > rA + 8) s[j][3] = NEGF;
                }
            }

            float mxA = NEGF, mxB = NEGF;
#pragma unroll
            for (int j = 0; j < 8; j++) {
                mxA = fmaxf(mxA, fmaxf(s[j][0], s[j][1]));
                mxB = fmaxf(mxB, fmaxf(s[j][2], s[j][3]));
            }
            mxA = fmaxf(mxA, __shfl_xor_sync(0xffffffffu, mxA, 1));
            mxA = fmaxf(mxA, __shfl_xor_sync(0xffffffffu, mxA, 2));
            mxB = fmaxf(mxB, __shfl_xor_sync(0xffffffffu, mxB, 1));
            mxB = fmaxf(mxB, __shfl_xor_sync(0xffffffffu, mxB, 2));
            float mAn = fmaxf(mA, mxA), mBn = fmaxf(mB, mxB);
            float fA = __expf(mA - mAn), fB = __expf(mB - mBn);
            float sA = 0.f, sB = 0.f;
#pragma unroll
            for (int j = 0; j < 8; j++) {
                s[j][0] = __expf(s[j][0] - mAn);
                s[j][1] = __expf(s[j][1] - mAn);
                s[j][2] = __expf(s[j][2] - mBn);
                s[j][3] = __expf(s[j][3] - mBn);
                sA += s[j][0] + s[j][1];
                sB += s[j][2] + s[j][3];
            }
            sA += __shfl_xor_sync(0xffffffffu, sA, 1);
            sA += __shfl_xor_sync(0xffffffffu, sA, 2);
            sB += __shfl_xor_sync(0xffffffffu, sB, 1);
            sB += __shfl_xor_sync(0xffffffffu, sB, 2);
            lA = lA * fA + sA;
            lB = lB * fB + sB;
            mA = mAn;
            mB = mBn;
#pragma unroll
            for (int j = 0; j < 16; j++) {
                o[j][0] *= fA;
                o[j][1] *= fA;
                o[j][2] *= fB;
                o[j][3] *= fB;
            }

#pragma unroll
            for (int kc = 0; kc < 4; kc++) {
                const int j0 = 2 * kc, j1 = 2 * kc + 1;
                unsigned ph[4], pl[4];
                ph[0] = pack_bf2(s[j0][0], s[j0][1]);
                ph[1] = pack_bf2(s[j0][2], s[j0][3]);
                ph[2] = pack_bf2(s[j1][0], s[j1][1]);
                ph[3] = pack_bf2(s[j1][2], s[j1][3]);
                pl[0] = pack_bf2(s[j0][0] - bf2lo(ph[0]), s[j0][1] - bf2hi(ph[0]));
                pl[1] = pack_bf2(s[j0][2] - bf2lo(ph[1]), s[j0][3] - bf2hi(ph[1]));
                pl[2] = pack_bf2(s[j1][0] - bf2lo(ph[2]), s[j1][1] - bf2hi(ph[2]));
                pl[3] = pack_bf2(s[j1][2] - bf2lo(ph[3]), s[j1][3] - bf2hi(ph[3]));
#pragma unroll
                for (int j = 0; j < 16; j++) {
                    uint32_t va = vb + (uint32_t)(kc * 16 + (lane & 15)) * (LDA * 2) +
                                  (uint32_t)(j * 8) * 2;
                    unsigned bvh[2], bvl[2];
                    ldsm2t(bvh, va);
                    ldsm2t(bvl, va + KARR);
                    mma16816(o[j], ph, bvh);
                    mma16816(o[j], ph, bvl);
                    mma16816(o[j], pl, bvh);
                }
            }
        }
        __syncthreads();
    }

    float rlA = 1.0f / lA, rlB = 1.0f / lB;
#pragma unroll
    for (int j = 0; j < 16; j++) {
        int c = h * HD + j * 8 + (lane & 3) * 2;
        float a0 = o[j][0] * rlA, a1 = o[j][1] * rlA;
        float b0 = o[j][2] * rlB, b1 = o[j][3] * rlB;
        unsigned hA = pack_bf2(a0, a1);
        unsigned lAp = pack_bf2(a0 - bf2lo(hA), a1 - bf2hi(hA));
        unsigned hB = pack_bf2(b0, b1);
        unsigned lBp = pack_bf2(b0 - bf2lo(hB), b1 - bf2hi(hB));
        *(unsigned*)(Oh + (size_t)rA * DIM + c) = hA;
        *(unsigned*)(Ol + (size_t)rA * DIM + c) = lAp;
        *(unsigned*)(Oh + (size_t)(rA + 8) * DIM + c) = hB;
        *(unsigned*)(Ol + (size_t)(rA + 8) * DIM + c) = lBp;
    }
}

// ---------------- launch --------------------------------------------------------
extern "C" void kernel_launch(void* const* d_in, const int* in_sizes, int n_in,
                              void* d_out, int out_size) {
    const float* x  = (const float*)d_in[0];
    const float* wq = (const float*)d_in[1];
    const float* wk = (const float*)d_in[2];
    const float* wv = (const float*)d_in[3];
    const float* wo = (const float*)d_in[4];
    const float* fc = (const float*)d_in[5];
    const float* fs = (const float*)d_in[6];
    float* out = (float*)d_out;

    __nv_bfloat16 *xh, *xl, *ah, *al, *qh, *ql, *kh, *kl, *vh, *vl, *wh, *wl, *woh, *wol;
    cudaGetSymbolAddress((void**)&xh, g_xh);
    cudaGetSymbolAddress((void**)&xl, g_xl);
    cudaGetSymbolAddress((void**)&ah, g_ah);
    cudaGetSymbolAddress((void**)&al, g_al);
    cudaGetSymbolAddress((void**)&qh, g_qh);
    cudaGetSymbolAddress((void**)&ql, g_ql);
    cudaGetSymbolAddress((void**)&kh, g_kh);
    cudaGetSymbolAddress((void**)&kl, g_kl);
    cudaGetSymbolAddress((void**)&vh, g_vh);
    cudaGetSymbolAddress((void**)&vl, g_vl);
    cudaGetSymbolAddress((void**)&wh, g_wh);
    cudaGetSymbolAddress((void**)&wl, g_wl);
    cudaGetSymbolAddress((void**)&woh, g_woh);
    cudaGetSymbolAddress((void**)&wol, g_wol);

    dim3 tsb(32, 8);
    transpose_split_qkv<<<dim3(NQKV / 32, DIM / 32), tsb>>>(wq, wk, wv, wh, wl);
    transpose_split<<<dim3(DIM / 32, DIM / 32), tsb>>>(wo, woh, wol, DIM, DIM);
    split_kernel<<<(SEQ * DIM + 255) / 256, 256>>>(x, xh, xl, SEQ * DIM);

    cudaFuncSetAttribute(gemm_hmma<0>, cudaFuncAttributeMaxDynamicSharedMemorySize, SMEM_GEMM);
    cudaFuncSetAttribute(gemm_hmma<1>, cudaFuncAttributeMaxDynamicSharedMemorySize, SMEM_GEMM);

    // QKV projection with fused RoPE + split epilogue (MODE 1), persistent grid
    gemm_hmma<1><<<PERSIST, 128, SMEM_GEMM>>>(
        xh, xl, wh, wl, nullptr, fc, fs, qh, ql, kh, kl, vh, vl, SEQ, NQKV, DIM);

    cudaFuncSetAttribute(attn_mma, cudaFuncAttributeMaxDynamicSharedMemorySize, SMEM_ATT);
    attn_mma<<<dim3(SEQ / AQ, NH), 256, SMEM_ATT>>>(qh, ql, kh, kl, vh, vl, ah, al);

    // output projection (MODE 0, fp32 out), persistent grid
    gemm_hmma<0><<<PERSIST, 128, SMEM_GEMM>>>(
        ah, al, woh, wol, out, nullptr, nullptr,
        nullptr, nullptr, nullptr, nullptr, nullptr, nullptr, SEQ, DIM, DIM);
}

// round 13
// speedup vs baseline: 1.1768x; 1.1768x over previous
#include <cuda_runtime.h>
#include <cuda_bf16.h>
#include <cstdint>

#define SEQ 2048
#define DIM 4096
#define NH 32
#define NKV 8
#define HD 128
#define KVD 1024   // NKV*HD
#define NQKV 6144  // DIM + 2*KVD

// ---------------- scratch (device globals) ----------------
__device__ __align__(128) __nv_bfloat16 g_xh[SEQ * DIM];
__device__ __align__(128) __nv_bfloat16 g_xl[SEQ * DIM];
__device__ __align__(128) __nv_bfloat16 g_ah[SEQ * DIM];
__device__ __align__(128) __nv_bfloat16 g_al[SEQ * DIM];
__device__ __align__(128) __nv_bfloat16 g_qh[SEQ * DIM];
__device__ __align__(128) __nv_bfloat16 g_ql[SEQ * DIM];
__device__ __align__(128) __nv_bfloat16 g_kh[SEQ * KVD];
__device__ __align__(128) __nv_bfloat16 g_kl[SEQ * KVD];
__device__ __align__(128) __nv_bfloat16 g_vh[SEQ * KVD];
__device__ __align__(128) __nv_bfloat16 g_vl[SEQ * KVD];
__device__ __align__(128) __nv_bfloat16 g_wh[NQKV * DIM];
__device__ __align__(128) __nv_bfloat16 g_wl[NQKV * DIM];
__device__ __align__(128) __nv_bfloat16 g_woh[DIM * DIM];
__device__ __align__(128) __nv_bfloat16 g_wol[DIM * DIM];

// ---------------- PTX helpers (baseline-PTX, sm_80-class) ----------------
__device__ __forceinline__ uint32_t smem_u32(const void* p) {
    uint32_t a;
    asm("{ .reg .u64 t; cvta.to.shared.u64 t, %1; cvt.u32.u64 %0, t; }" : "=r"(a) : "l"(p));
    return a;
}
__device__ __forceinline__ void cpa16(uint32_t s, const void* g) {
    asm volatile("cp.async.cg.shared.global [%0], [%1], 16;" :: "r"(s), "l"(g));
}
__device__ __forceinline__ void ldsm4(unsigned* r, uint32_t addr) {
    asm volatile("ldmatrix.sync.aligned.m8n8.x4.shared.b16 {%0,%1,%2,%3}, [%4];"
                 : "=r"(r[0]), "=r"(r[1]), "=r"(r[2]), "=r"(r[3]) : "r"(addr));
}
__device__ __forceinline__ void ldsm2(unsigned* r, uint32_t addr) {
    asm volatile("ldmatrix.sync.aligned.m8n8.x2.shared.b16 {%0,%1}, [%2];"
                 : "=r"(r[0]), "=r"(r[1]) : "r"(addr));
}
__device__ __forceinline__ void ldsm4t(unsigned* r, uint32_t addr) {
    asm volatile("ldmatrix.sync.aligned.m8n8.x4.trans.shared.b16 {%0,%1,%2,%3}, [%4];"
                 : "=r"(r[0]), "=r"(r[1]), "=r"(r[2]), "=r"(r[3]) : "r"(addr));
}
__device__ __forceinline__ void mma16816(float* d, const unsigned* a, const unsigned* b) {
    asm volatile(
        "mma.sync.aligned.m16n8k16.row.col.f32.bf16.bf16.f32 "
        "{%0,%1,%2,%3}, {%4,%5,%6,%7}, {%8,%9}, {%0,%1,%2,%3};"
        : "+f"(d[0]), "+f"(d[1]), "+f"(d[2]), "+f"(d[3])
        : "r"(a[0]), "r"(a[1]), "r"(a[2]), "r"(a[3]), "r"(b[0]), "r"(b[1]));
}
__device__ __forceinline__ unsigned pack_bf2(float lo, float hi) {
    unsigned d;
    asm("cvt.rn.bf16x2.f32 %0, %1, %2;" : "=r"(d) : "f"(hi), "f"(lo));
    return d;
}
__device__ __forceinline__ float bf2lo(unsigned r) { return __uint_as_float(r << 16); }
__device__ __forceinline__ float bf2hi(unsigned r) { return __uint_as_float(r & 0xffff0000u); }

// ---------------- conversion kernels ----------------
__global__ void split_kernel(const float* __restrict__ x, __nv_bfloat16* __restrict__ h,
                             __nv_bfloat16* __restrict__ l, int n) {
    int i = blockIdx.x * blockDim.x + threadIdx.x;
    if (i >= n) return;
    float v = x[i];
    __nv_bfloat16 hi = __float2bfloat16(v);
    __nv_bfloat16 lo = __float2bfloat16(v - __bfloat162float(hi));
    h[i] = hi;
    l[i] = lo;
}

__global__ void transpose_split_qkv(const float* __restrict__ wq, const float* __restrict__ wk,
                                    const float* __restrict__ wv,
                                    __nv_bfloat16* __restrict__ th, __nv_bfloat16* __restrict__ tl) {
    __shared__ float tile[32][33];
    int k0 = blockIdx.y * 32, n0 = blockIdx.x * 32;
    int tx = threadIdx.x, ty = threadIdx.y;   // 32 x 8
    const float* src;
    int nn0, ldn;
    if (n0 < DIM) { src = wq; nn0 = n0; ldn = DIM; }
    else if (n0 < DIM + KVD) { src = wk; nn0 = n0 - DIM; ldn = KVD; }
    else { src = wv; nn0 = n0 - DIM - KVD; ldn = KVD; }
#pragma unroll
    for (int r = 0; r < 4; r++)
        tile[ty + r * 8][tx] = src[(size_t)(k0 + ty + r * 8) * ldn + nn0 + tx];
    __syncthreads();
#pragma unroll
    for (int r = 0; r < 4; r++) {
        float v = tile[tx][ty + r * 8];
        __nv_bfloat16 hi = __float2bfloat16(v);
        __nv_bfloat16 lo = __float2bfloat16(v - __bfloat162float(hi));
        size_t o = (size_t)(n0 + ty + r * 8) * DIM + k0 + tx;
        th[o] = hi;
        tl[o] = lo;
    }
}

__global__ void transpose_split(const float* __restrict__ w, __nv_bfloat16* __restrict__ th,
                                __nv_bfloat16* __restrict__ tl, int K, int N) {
    __shared__ float tile[32][33];
    int k0 = blockIdx.y * 32, n0 = blockIdx.x * 32;
    int tx = threadIdx.x, ty = threadIdx.y;
#pragma unroll
    for (int r = 0; r < 4; r++)
        tile[ty + r * 8][tx] = w[(size_t)(k0 + ty + r * 8) * N + n0 + tx];
    __syncthreads();
#pragma unroll
    for (int r = 0; r < 4; r++) {
        float v = tile[tx][ty + r * 8];
        __nv_bfloat16 hi = __float2bfloat16(v);
        __nv_bfloat16 lo = __float2bfloat16(v - __bfloat162float(hi));
        size_t o = (size_t)(n0 + ty + r * 8) * K + k0 + tx;
        th[o] = hi;
        tl[o] = lo;
    }
}

// ---------------- HMMA bf16x3 GEMM (R10, FROZEN — measured best) ----------------
#define BM 128
#define BN 128
#define BK 32
#define LDE 40                     // padded bf16/row (80B: conflict-free LDSM)
#define ARR (128 * LDE * 2)        // 10240 B
#define STG (4 * ARR)              // 40960 B per stage
#define SMEM_GEMM (2 * STG)        // 81920 B

template <int MODE>
__global__ __launch_bounds__(128, 2)
void gemm_hmma(const __nv_bfloat16* __restrict__ Ah, const __nv_bfloat16* __restrict__ Al,
               const __nv_bfloat16* __restrict__ Bh, const __nv_bfloat16* __restrict__ Bl,
               float* __restrict__ C,
               const float* __restrict__ cs, const float* __restrict__ sn,
               __nv_bfloat16* __restrict__ qh, __nv_bfloat16* __restrict__ ql,
               __nv_bfloat16* __restrict__ kh, __nv_bfloat16* __restrict__ kl,
               __nv_bfloat16* __restrict__ vh, __nv_bfloat16* __restrict__ vl,
               int M, int N, int K) {
    extern __shared__ char smem[];
    const uint32_t sb = smem_u32(smem);
    const int tid = threadIdx.x;
    const int lane = tid & 31, warp = tid >> 5;
    const int m0 = blockIdx.y * BM, n0 = blockIdx.x * BN;
    const int wm = (warp & 1) * 64, wn = (warp >> 1) * 64;

    float acc[4][8][4];
#pragma unroll
    for (int m = 0; m < 4; m++)
#pragma unroll
        for (int j = 0; j < 8; j++)
#pragma unroll
            for (int v = 0; v < 4; v++) acc[m][j][v] = 0.f;

    auto load_stage = [&](int buf, int ko) {
        uint32_t s0 = sb + buf * STG;
#pragma unroll
        for (int s = tid; s < 512; s += 128) {
            int row = s >> 2, c = s & 3;
            uint32_t so = s0 + (uint32_t)row * (LDE * 2) + c * 16;
            size_t go = (size_t)row * K + ko + c * 8;
            cpa16(so, Ah + (size_t)m0 * K + go);
            cpa16(so + ARR, Al + (size_t)m0 * K + go);
            cpa16(so + 2 * ARR, Bh + (size_t)n0 * K + go);
            cpa16(so + 3 * ARR, Bl + (size_t)n0 * K + go);
        }
        asm volatile("cp.async.commit_group;");
    };

    load_stage(0, 0);
    const int NS = K / BK;
#pragma unroll 1
    for (int s = 0; s < NS; s++) {
        if (s + 1 < NS) {
            load_stage((s + 1) & 1, (s + 1) * BK);
            asm volatile("cp.async.wait_group 1;");
        } else {
            asm volatile("cp.async.wait_group 0;");
        }
        __syncthreads();

        const uint32_t base = sb + (s & 1) * STG;
#pragma unroll
        for (int ks = 0; ks < 2; ks++) {
            const int k0 = ks * 16;
            unsigned ah[4][4], al[4][4];
#pragma unroll
            for (int m = 0; m < 4; m++) {
                uint32_t aa = base +
                    (uint32_t)(wm + m * 16 + (lane & 15)) * (LDE * 2) +
                    (uint32_t)(k0 + (lane >> 4) * 8) * 2;
                ldsm4(ah[m], aa);
                ldsm4(al[m], aa + ARR);
            }
#pragma unroll
            for (int j = 0; j < 8; j++) {
                uint32_t ba = base + 2 * ARR +
                    (uint32_t)(wn + j * 8 + (lane & 7)) * (LDE * 2) +
                    (uint32_t)(k0 + ((lane >> 3) & 1) * 8) * 2;
                unsigned bh[2], bl[2];
                ldsm2(bh, ba);
                ldsm2(bl, ba + ARR);
#pragma unroll
                for (int m = 0; m < 4; m++) {
                    mma16816(acc[m][j], ah[m], bh);
                    mma16816(acc[m][j], ah[m], bl);
                    mma16816(acc[m][j], al[m], bh);
                }
            }
        }
        __syncthreads();
    }

    if (MODE == 0) {
#pragma unroll
        for (int m = 0; m < 4; m++) {
            int r0 = m0 + wm + m * 16 + (lane >> 2);
#pragma unroll
            for (int j = 0; j < 8; j++) {
                int c = n0 + wn + j * 8 + (lane & 3) * 2;
                *(float2*)(C + (size_t)r0 * N + c) = make_float2(acc[m][j][0], acc[m][j][1]);
                *(float2*)(C + (size_t)(r0 + 8) * N + c) =
                    make_float2(acc[m][j][2], acc[m][j][3]);
            }
        }
    } else {
        // fused RoPE + bf16 hi/lo split; CTA's n-range lies entirely in Q, K, or V.
        __nv_bfloat16 *oh, *ol;
        int ld, nbase;
        bool rope;
        if (n0 < DIM) { oh = qh; ol = ql; ld = DIM; nbase = 0; rope = true; }
        else if (n0 < DIM + KVD) { oh = kh; ol = kl; ld = KVD; nbase = DIM; rope = true; }
        else { oh = vh; ol = vl; ld = KVD; nbase = DIM + KVD; rope = false; }
#pragma unroll
        for (int m = 0; m < 4; m++) {
            int r0 = m0 + wm + m * 16 + (lane >> 2);
#pragma unroll
            for (int j = 0; j < 8; j++) {
                int c = n0 + wn + j * 8 + (lane & 3) * 2;
                float a0 = acc[m][j][0], a1 = acc[m][j][1];   // row r0
                float b0 = acc[m][j][2], b1 = acc[m][j][3];   // row r0+8
                if (rope) {
                    int i = (c & 127) >> 1;
                    float c0 = cs[r0 * 64 + i], s0 = sn[r0 * 64 + i];
                    float c1 = cs[(r0 + 8) * 64 + i], s1 = sn[(r0 + 8) * 64 + i];
                    float t0 = a0 * c0 - a1 * s0, t1 = a0 * s0 + a1 * c0;
                    a0 = t0; a1 = t1;
                    t0 = b0 * c1 - b1 * s1; t1 = b0 * s1 + b1 * c1;
                    b0 = t0; b1 = t1;
                }
                int cl = c - nbase;
                unsigned hA = pack_bf2(a0, a1);
                unsigned lA = pack_bf2(a0 - bf2lo(hA), a1 - bf2hi(hA));
                unsigned hB = pack_bf2(b0, b1);
                unsigned lB = pack_bf2(b0 - bf2lo(hB), b1 - bf2hi(hB));
                *(unsigned*)(oh + (size_t)r0 * ld + cl) = hA;
                *(unsigned*)(ol + (size_t)r0 * ld + cl) = lA;
                *(unsigned*)(oh + (size_t)(r0 + 8) * ld + cl) = hB;
                *(unsigned*)(ol + (size_t)(r0 + 8) * ld + cl) = lB;
            }
        }
    }
}

// ---------------- tensorized flash attention (x4 LDSM for K/V fragments) --------
#define AQ 128
#define AKV 64
#define LDA 136
#define QARR (128 * LDA * 2)
#define KARR (64 * LDA * 2)
#define KVSTG (4 * KARR)
#define SMEM_ATT (2 * QARR + 2 * KVSTG)   // 208896 B

__global__ __launch_bounds__(256, 1)
void attn_mma(const __nv_bfloat16* __restrict__ Qh, const __nv_bfloat16* __restrict__ Ql,
              const __nv_bfloat16* __restrict__ Kh, const __nv_bfloat16* __restrict__ Kl,
              const __nv_bfloat16* __restrict__ Vh, const __nv_bfloat16* __restrict__ Vl,
              __nv_bfloat16* __restrict__ Oh, __nv_bfloat16* __restrict__ Ol) {
    extern __shared__ char smem[];
    const uint32_t sb = smem_u32(smem);
    const int tid = threadIdx.x;
    const int lane = tid & 31, warp = tid >> 5;
    const int h = blockIdx.y;
    const int qt = (gridDim.x - 1) - blockIdx.x;
    const int q0 = qt * AQ;
    const int kvh = h >> 2;
    const float scale = 0.08838834764831845f;
    const float NEGF = -1e30f;

#pragma unroll
    for (int s = tid; s < 128 * 16; s += 256) {
        int row = s >> 4, c = s & 15;
        uint32_t so = sb + (uint32_t)row * (LDA * 2) + c * 16;
        size_t go = (size_t)(q0 + row) * DIM + h * HD + c * 8;
        cpa16(so, Qh + go);
        cpa16(so + QARR, Ql + go);
    }
    auto load_kv = [&](int buf, int k0) {
        uint32_t b0 = sb + 2 * QARR + buf * KVSTG;
#pragma unroll
        for (int s = tid; s < 1024; s += 256) {
            int row = s >> 4, c = s & 15;
            uint32_t so = b0 + (uint32_t)row * (LDA * 2) + c * 16;
            size_t go = (size_t)(k0 + row) * KVD + kvh * HD + c * 8;
            cpa16(so, Kh + go);
            cpa16(so + KARR, Kl + go);
            cpa16(so + 2 * KARR, Vh + go);
            cpa16(so + 3 * KARR, Vl + go);
        }
        asm volatile("cp.async.commit_group;");
    };
    load_kv(0, 0);

    const int rA = q0 + warp * 16 + (lane >> 2);
    const int qwmax = q0 + warp * 16 + 15;
    float mA = NEGF, mB = NEGF, lA = 0.f, lB = 0.f;
    float o[16][4];
#pragma unroll
    for (int j = 0; j < 16; j++)
#pragma unroll
        for (int v = 0; v < 4; v++) o[j][v] = 0.f;

    const int ntiles = (q0 + AQ) / AKV;
#pragma unroll 1
    for (int t = 0; t < ntiles; t++) {
        const int k0 = t * AKV;
        if (t + 1 < ntiles) {
            load_kv((t + 1) & 1, (t + 1) * AKV);
            asm volatile("cp.async.wait_group 1;");
        } else {
            asm volatile("cp.async.wait_group 0;");
        }
        __syncthreads();

        if (k0 <= qwmax) {
            const uint32_t kb = sb + 2 * QARR + (t & 1) * KVSTG;
            const uint32_t vb = kb + 2 * KARR;

            float s[8][4];
#pragma unroll
            for (int j = 0; j < 8; j++)
#pragma unroll
                for (int v = 0; v < 4; v++) s[j][v] = 0.f;

            // S = Q K^T; K fragments via x4 (two j-subtiles per ldmatrix)
#pragma unroll
            for (int kc = 0; kc < 8; kc++) {
                uint32_t qa = sb + (uint32_t)(warp * 16 + (lane & 15)) * (LDA * 2) +
                              (uint32_t)(kc * 16 + (lane >> 4) * 8) * 2;
                unsigned aqh[4], aql[4];
                ldsm4(aqh, qa);
                ldsm4(aql, qa + QARR);
#pragma unroll
                for (int jj = 0; jj < 4; jj++) {
                    // rows jj*16 + ((lane>>4)&1)*8 + (lane&7); col kc*16 + ((lane>>3)&1)*8
                    uint32_t ka = kb +
                        (uint32_t)(jj * 16 + ((lane >> 4) & 1) * 8 + (lane & 7)) * (LDA * 2) +
                        (uint32_t)(kc * 16 + ((lane >> 3) & 1) * 8) * 2;
                    unsigned bkh[4], bkl[4];
                    ldsm4(bkh, ka);
                    ldsm4(bkl, ka + KARR);
                    mma16816(s[2 * jj], aqh, bkh);
                    mma16816(s[2 * jj], aqh, bkl);
                    mma16816(s[2 * jj], aql, bkh);
                    mma16816(s[2 * jj + 1], aqh, bkh + 2);
                    mma16816(s[2 * jj + 1], aqh, bkl + 2);
                    mma16816(s[2 * jj + 1], aql, bkh + 2);
                }
            }

            const bool need_mask = (k0 + AKV - 1) > (q0 + warp * 16);
#pragma unroll
            for (int j = 0; j < 8; j++) {
#pragma unroll
                for (int v = 0; v < 4; v++) s[j][v] *= scale;
                if (need_mask) {
                    int cg = k0 + j * 8 + (lane & 3) * 2;
                    if (cg > rA) s[j][0] = NEGF;
                    if (cg + 1 > rA) s[j][1] = NEGF;
                    if (cg > rA + 8) s[j][2] = NEGF;
                    if (cg + 1 > rA + 8) s[j][3] = NEGF;
                }
            }

            float mxA = NEGF, mxB = NEGF;
#pragma unroll
            for (int j = 0; j < 8; j++) {
                mxA = fmaxf(mxA, fmaxf(s[j][0], s[j][1]));
                mxB = fmaxf(mxB, fmaxf(s[j][2], s[j][3]));
            }
            mxA = fmaxf(mxA, __shfl_xor_sync(0xffffffffu, mxA, 1));
            mxA = fmaxf(mxA, __shfl_xor_sync(0xffffffffu, mxA, 2));
            mxB = fmaxf(mxB, __shfl_xor_sync(0xffffffffu, mxB, 1));
            mxB = fmaxf(mxB, __shfl_xor_sync(0xffffffffu, mxB, 2));
            float mAn = fmaxf(mA, mxA), mBn = fmaxf(mB, mxB);
            float fA = __expf(mA - mAn), fB = __expf(mB - mBn);
            float sA = 0.f, sB = 0.f;
#pragma unroll
            for (int j = 0; j < 8; j++) {
                s[j][0] = __expf(s[j][0] - mAn);
                s[j][1] = __expf(s[j][1] - mAn);
                s[j][2] = __expf(s[j][2] - mBn);
                s[j][3] = __expf(s[j][3] - mBn);
                sA += s[j][0] + s[j][1];
                sB += s[j][2] + s[j][3];
            }
            sA += __shfl_xor_sync(0xffffffffu, sA, 1);
            sA += __shfl_xor_sync(0xffffffffu, sA, 2);
            sB += __shfl_xor_sync(0xffffffffu, sB, 1);
            sB += __shfl_xor_sync(0xffffffffu, sB, 2);
            lA = lA * fA + sA;
            lB = lB * fB + sB;
            mA = mAn;
            mB = mBn;
#pragma unroll
            for (int j = 0; j < 16; j++) {
                o[j][0] *= fA;
                o[j][1] *= fA;
                o[j][2] *= fB;
                o[j][3] *= fB;
            }

            // O += P V; V^T fragments via x4 trans (two j-subtiles per ldmatrix)
#pragma unroll
            for (int kc = 0; kc < 4; kc++) {
                const int j0 = 2 * kc, j1 = 2 * kc + 1;
                unsigned ph[4], pl[4];
                ph[0] = pack_bf2(s[j0][0], s[j0][1]);
                ph[1] = pack_bf2(s[j0][2], s[j0][3]);
                ph[2] = pack_bf2(s[j1][0], s[j1][1]);
                ph[3] = pack_bf2(s[j1][2], s[j1][3]);
                pl[0] = pack_bf2(s[j0][0] - bf2lo(ph[0]), s[j0][1] - bf2hi(ph[0]));
                pl[1] = pack_bf2(s[j0][2] - bf2lo(ph[1]), s[j0][3] - bf2hi(ph[1]));
                pl[2] = pack_bf2(s[j1][0] - bf2lo(ph[2]), s[j1][1] - bf2hi(ph[2]));
                pl[3] = pack_bf2(s[j1][2] - bf2lo(ph[3]), s[j1][3] - bf2hi(ph[3]));
#pragma unroll
                for (int jj = 0; jj < 8; jj++) {
                    // rows kc*16 + (lane&15); col (2*jj + (lane>>4))*8
                    uint32_t va = vb +
                        (uint32_t)(kc * 16 + (lane & 15)) * (LDA * 2) +
                        (uint32_t)((2 * jj + (lane >> 4)) * 8) * 2;
                    unsigned bvh[4], bvl[4];
                    ldsm4t(bvh, va);
                    ldsm4t(bvl, va + KARR);
                    mma16816(o[2 * jj], ph, bvh);
                    mma16816(o[2 * jj], ph, bvl);
                    mma16816(o[2 * jj], pl, bvh);
                    mma16816(o[2 * jj + 1], ph, bvh + 2);
                    mma16816(o[2 * jj + 1], ph, bvl + 2);
                    mma16816(o[2 * jj + 1], pl, bvh + 2);
                }
            }
        }
        __syncthreads();
    }

    float rlA = 1.0f / lA, rlB = 1.0f / lB;
#pragma unroll
    for (int j = 0; j < 16; j++) {
        int c = h * HD + j * 8 + (lane & 3) * 2;
        float a0 = o[j][0] * rlA, a1 = o[j][1] * rlA;
        float b0 = o[j][2] * rlB, b1 = o[j][3] * rlB;
        unsigned hA = pack_bf2(a0, a1);
        unsigned lAp = pack_bf2(a0 - bf2lo(hA), a1 - bf2hi(hA));
        unsigned hB = pack_bf2(b0, b1);
        unsigned lBp = pack_bf2(b0 - bf2lo(hB), b1 - bf2hi(hB));
        *(unsigned*)(Oh + (size_t)rA * DIM + c) = hA;
        *(unsigned*)(Ol + (size_t)rA * DIM + c) = lAp;
        *(unsigned*)(Oh + (size_t)(rA + 8) * DIM + c) = hB;
        *(unsigned*)(Ol + (size_t)(rA + 8) * DIM + c) = lBp;
    }
}

// ---------------- launch --------------------------------------------------------
extern "C" void kernel_launch(void* const* d_in, const int* in_sizes, int n_in,
                              void* d_out, int out_size) {
    const float* x  = (const float*)d_in[0];
    const float* wq = (const float*)d_in[1];
    const float* wk = (const float*)d_in[2];
    const float* wv = (const float*)d_in[3];
    const float* wo = (const float*)d_in[4];
    const float* fc = (const float*)d_in[5];
    const float* fs = (const float*)d_in[6];
    float* out = (float*)d_out;

    __nv_bfloat16 *xh, *xl, *ah, *al, *qh, *ql, *kh, *kl, *vh, *vl, *wh, *wl, *woh, *wol;
    cudaGetSymbolAddress((void**)&xh, g_xh);
    cudaGetSymbolAddress((void**)&xl, g_xl);
    cudaGetSymbolAddress((void**)&ah, g_ah);
    cudaGetSymbolAddress((void**)&al, g_al);
    cudaGetSymbolAddress((void**)&qh, g_qh);
    cudaGetSymbolAddress((void**)&ql, g_ql);
    cudaGetSymbolAddress((void**)&kh, g_kh);
    cudaGetSymbolAddress((void**)&kl, g_kl);
    cudaGetSymbolAddress((void**)&vh, g_vh);
    cudaGetSymbolAddress((void**)&vl, g_vl);
    cudaGetSymbolAddress((void**)&wh, g_wh);
    cudaGetSymbolAddress((void**)&wl, g_wl);
    cudaGetSymbolAddress((void**)&woh, g_woh);
    cudaGetSymbolAddress((void**)&wol, g_wol);

    dim3 tsb(32, 8);
    transpose_split_qkv<<<dim3(NQKV / 32, DIM / 32), tsb>>>(wq, wk, wv, wh, wl);
    transpose_split<<<dim3(DIM / 32, DIM / 32), tsb>>>(wo, woh, wol, DIM, DIM);
    split_kernel<<<(SEQ * DIM + 255) / 256, 256>>>(x, xh, xl, SEQ * DIM);

    cudaFuncSetAttribute(gemm_hmma<0>, cudaFuncAttributeMaxDynamicSharedMemorySize, SMEM_GEMM);
    cudaFuncSetAttribute(gemm_hmma<1>, cudaFuncAttributeMaxDynamicSharedMemorySize, SMEM_GEMM);

    // QKV projection with fused RoPE + split epilogue (compile-time MODE 1)
    gemm_hmma<1><<<dim3(NQKV / BN, SEQ / BM), 128, SMEM_GEMM>>>(
        xh, xl, wh, wl, nullptr, fc, fs, qh, ql, kh, kl, vh, vl, SEQ, NQKV, DIM);

    cudaFuncSetAttribute(attn_mma, cudaFuncAttributeMaxDynamicSharedMemorySize, SMEM_ATT);
    attn_mma<<<dim3(SEQ / AQ, NH), 256, SMEM_ATT>>>(qh, ql, kh, kl, vh, vl, ah, al);

    // output projection (compile-time MODE 0, fp32 out)
    gemm_hmma<0><<<dim3(DIM / BN, SEQ / BM), 128, SMEM_GEMM>>>(
        ah, al, woh, wol, out, nullptr, nullptr,
        nullptr, nullptr, nullptr, nullptr, nullptr, nullptr, SEQ, DIM, DIM);
}

// round 14
// speedup vs baseline: 1.1917x; 1.0127x over previous
#include <cuda_runtime.h>
#include <cuda_bf16.h>
#include <cstdint>

#define SEQ 2048
#define DIM 4096
#define NH 32
#define NKV 8
#define HD 128
#define KVD 1024   // NKV*HD
#define NQKV 6144  // DIM + 2*KVD

// ---------------- scratch (device globals) ----------------
__device__ __align__(128) __nv_bfloat16 g_xh[SEQ * DIM];
__device__ __align__(128) __nv_bfloat16 g_xl[SEQ * DIM];
__device__ __align__(128) __nv_bfloat16 g_ah[SEQ * DIM];
__device__ __align__(128) __nv_bfloat16 g_al[SEQ * DIM];
__device__ __align__(128) __nv_bfloat16 g_qh[SEQ * DIM];
__device__ __align__(128) __nv_bfloat16 g_ql[SEQ * DIM];
__device__ __align__(128) __nv_bfloat16 g_kh[SEQ * KVD];
__device__ __align__(128) __nv_bfloat16 g_kl[SEQ * KVD];
__device__ __align__(128) __nv_bfloat16 g_vh[SEQ * KVD];
__device__ __align__(128) __nv_bfloat16 g_vl[SEQ * KVD];
__device__ __align__(128) __nv_bfloat16 g_wh[NQKV * DIM];
__device__ __align__(128) __nv_bfloat16 g_wl[NQKV * DIM];
__device__ __align__(128) __nv_bfloat16 g_woh[DIM * DIM];
__device__ __align__(128) __nv_bfloat16 g_wol[DIM * DIM];

// ---------------- PTX helpers (baseline-PTX, sm_80-class) ----------------
__device__ __forceinline__ uint32_t smem_u32(const void* p) {
    uint32_t a;
    asm("{ .reg .u64 t; cvta.to.shared.u64 t, %1; cvt.u32.u64 %0, t; }" : "=r"(a) : "l"(p));
    return a;
}
__device__ __forceinline__ void cpa16(uint32_t s, const void* g) {
    asm volatile("cp.async.cg.shared.global [%0], [%1], 16;" :: "r"(s), "l"(g));
}
__device__ __forceinline__ void ldsm4(unsigned* r, uint32_t addr) {
    asm volatile("ldmatrix.sync.aligned.m8n8.x4.shared.b16 {%0,%1,%2,%3}, [%4];"
                 : "=r"(r[0]), "=r"(r[1]), "=r"(r[2]), "=r"(r[3]) : "r"(addr));
}
__device__ __forceinline__ void ldsm2(unsigned* r, uint32_t addr) {
    asm volatile("ldmatrix.sync.aligned.m8n8.x2.shared.b16 {%0,%1}, [%2];"
                 : "=r"(r[0]), "=r"(r[1]) : "r"(addr));
}
__device__ __forceinline__ void ldsm4t(unsigned* r, uint32_t addr) {
    asm volatile("ldmatrix.sync.aligned.m8n8.x4.trans.shared.b16 {%0,%1,%2,%3}, [%4];"
                 : "=r"(r[0]), "=r"(r[1]), "=r"(r[2]), "=r"(r[3]) : "r"(addr));
}
__device__ __forceinline__ void mma16816(float* d, const unsigned* a, const unsigned* b) {
    asm volatile(
        "mma.sync.aligned.m16n8k16.row.col.f32.bf16.bf16.f32 "
        "{%0,%1,%2,%3}, {%4,%5,%6,%7}, {%8,%9}, {%0,%1,%2,%3};"
        : "+f"(d[0]), "+f"(d[1]), "+f"(d[2]), "+f"(d[3])
        : "r"(a[0]), "r"(a[1]), "r"(a[2]), "r"(a[3]), "r"(b[0]), "r"(b[1]));
}
__device__ __forceinline__ unsigned pack_bf2(float lo, float hi) {
    unsigned d;
    asm("cvt.rn.bf16x2.f32 %0, %1, %2;" : "=r"(d) : "f"(hi), "f"(lo));
    return d;
}
__device__ __forceinline__ float bf2lo(unsigned r) { return __uint_as_float(r << 16); }
__device__ __forceinline__ float bf2hi(unsigned r) { return __uint_as_float(r & 0xffff0000u); }

// ---------------- conversion kernels ----------------
__global__ void split_kernel(const float* __restrict__ x, __nv_bfloat16* __restrict__ h,
                             __nv_bfloat16* __restrict__ l, int n) {
    int i = blockIdx.x * blockDim.x + threadIdx.x;
    if (i >= n) return;
    float v = x[i];
    __nv_bfloat16 hi = __float2bfloat16(v);
    __nv_bfloat16 lo = __float2bfloat16(v - __bfloat162float(hi));
    h[i] = hi;
    l[i] = lo;
}

__global__ void transpose_split_qkv(const float* __restrict__ wq, const float* __restrict__ wk,
                                    const float* __restrict__ wv,
                                    __nv_bfloat16* __restrict__ th, __nv_bfloat16* __restrict__ tl) {
    __shared__ float tile[32][33];
    int k0 = blockIdx.y * 32, n0 = blockIdx.x * 32;
    int tx = threadIdx.x, ty = threadIdx.y;   // 32 x 8
    const float* src;
    int nn0, ldn;
    if (n0 < DIM) { src = wq; nn0 = n0; ldn = DIM; }
    else if (n0 < DIM + KVD) { src = wk; nn0 = n0 - DIM; ldn = KVD; }
    else { src = wv; nn0 = n0 - DIM - KVD; ldn = KVD; }
#pragma unroll
    for (int r = 0; r < 4; r++)
        tile[ty + r * 8][tx] = src[(size_t)(k0 + ty + r * 8) * ldn + nn0 + tx];
    __syncthreads();
#pragma unroll
    for (int r = 0; r < 4; r++) {
        float v = tile[tx][ty + r * 8];
        __nv_bfloat16 hi = __float2bfloat16(v);
        __nv_bfloat16 lo = __float2bfloat16(v - __bfloat162float(hi));
        size_t o = (size_t)(n0 + ty + r * 8) * DIM + k0 + tx;
        th[o] = hi;
        tl[o] = lo;
    }
}

__global__ void transpose_split(const float* __restrict__ w, __nv_bfloat16* __restrict__ th,
                                __nv_bfloat16* __restrict__ tl, int K, int N) {
    __shared__ float tile[32][33];
    int k0 = blockIdx.y * 32, n0 = blockIdx.x * 32;
    int tx = threadIdx.x, ty = threadIdx.y;
#pragma unroll
    for (int r = 0; r < 4; r++)
        tile[ty + r * 8][tx] = w[(size_t)(k0 + ty + r * 8) * N + n0 + tx];
    __syncthreads();
#pragma unroll
    for (int r = 0; r < 4; r++) {
        float v = tile[tx][ty + r * 8];
        __nv_bfloat16 hi = __float2bfloat16(v);
        __nv_bfloat16 lo = __float2bfloat16(v - __bfloat162float(hi));
        size_t o = (size_t)(n0 + ty + r * 8) * K + k0 + tx;
        th[o] = hi;
        tl[o] = lo;
    }
}

// ---------------- HMMA bf16x3 GEMM (R10, FROZEN — measured best) ----------------
#define BM 128
#define BN 128
#define BK 32
#define LDE 40                     // padded bf16/row (80B: conflict-free LDSM)
#define ARR (128 * LDE * 2)        // 10240 B
#define STG (4 * ARR)              // 40960 B per stage
#define SMEM_GEMM (2 * STG)        // 81920 B

template <int MODE>
__global__ __launch_bounds__(128, 2)
void gemm_hmma(const __nv_bfloat16* __restrict__ Ah, const __nv_bfloat16* __restrict__ Al,
               const __nv_bfloat16* __restrict__ Bh, const __nv_bfloat16* __restrict__ Bl,
               float* __restrict__ C,
               const float* __restrict__ cs, const float* __restrict__ sn,
               __nv_bfloat16* __restrict__ qh, __nv_bfloat16* __restrict__ ql,
               __nv_bfloat16* __restrict__ kh, __nv_bfloat16* __restrict__ kl,
               __nv_bfloat16* __restrict__ vh, __nv_bfloat16* __restrict__ vl,
               int M, int N, int K) {
    extern __shared__ char smem[];
    const uint32_t sb = smem_u32(smem);
    const int tid = threadIdx.x;
    const int lane = tid & 31, warp = tid >> 5;
    const int m0 = blockIdx.y * BM, n0 = blockIdx.x * BN;
    const int wm = (warp & 1) * 64, wn = (warp >> 1) * 64;

    float acc[4][8][4];
#pragma unroll
    for (int m = 0; m < 4; m++)
#pragma unroll
        for (int j = 0; j < 8; j++)
#pragma unroll
            for (int v = 0; v < 4; v++) acc[m][j][v] = 0.f;

    auto load_stage = [&](int buf, int ko) {
        uint32_t s0 = sb + buf * STG;
#pragma unroll
        for (int s = tid; s < 512; s += 128) {
            int row = s >> 2, c = s & 3;
            uint32_t so = s0 + (uint32_t)row * (LDE * 2) + c * 16;
            size_t go = (size_t)row * K + ko + c * 8;
            cpa16(so, Ah + (size_t)m0 * K + go);
            cpa16(so + ARR, Al + (size_t)m0 * K + go);
            cpa16(so + 2 * ARR, Bh + (size_t)n0 * K + go);
            cpa16(so + 3 * ARR, Bl + (size_t)n0 * K + go);
        }
        asm volatile("cp.async.commit_group;");
    };

    load_stage(0, 0);
    const int NS = K / BK;
#pragma unroll 1
    for (int s = 0; s < NS; s++) {
        if (s + 1 < NS) {
            load_stage((s + 1) & 1, (s + 1) * BK);
            asm volatile("cp.async.wait_group 1;");
        } else {
            asm volatile("cp.async.wait_group 0;");
        }
        __syncthreads();

        const uint32_t base = sb + (s & 1) * STG;
#pragma unroll
        for (int ks = 0; ks < 2; ks++) {
            const int k0 = ks * 16;
            unsigned ah[4][4], al[4][4];
#pragma unroll
            for (int m = 0; m < 4; m++) {
                uint32_t aa = base +
                    (uint32_t)(wm + m * 16 + (lane & 15)) * (LDE * 2) +
                    (uint32_t)(k0 + (lane >> 4) * 8) * 2;
                ldsm4(ah[m], aa);
                ldsm4(al[m], aa + ARR);
            }
#pragma unroll
            for (int j = 0; j < 8; j++) {
                uint32_t ba = base + 2 * ARR +
                    (uint32_t)(wn + j * 8 + (lane & 7)) * (LDE * 2) +
                    (uint32_t)(k0 + ((lane >> 3) & 1) * 8) * 2;
                unsigned bh[2], bl[2];
                ldsm2(bh, ba);
                ldsm2(bl, ba + ARR);
#pragma unroll
                for (int m = 0; m < 4; m++) {
                    mma16816(acc[m][j], ah[m], bh);
                    mma16816(acc[m][j], ah[m], bl);
                    mma16816(acc[m][j], al[m], bh);
                }
            }
        }
        __syncthreads();
    }

    if (MODE == 0) {
#pragma unroll
        for (int m = 0; m < 4; m++) {
            int r0 = m0 + wm + m * 16 + (lane >> 2);
#pragma unroll
            for (int j = 0; j < 8; j++) {
                int c = n0 + wn + j * 8 + (lane & 3) * 2;
                *(float2*)(C + (size_t)r0 * N + c) = make_float2(acc[m][j][0], acc[m][j][1]);
                *(float2*)(C + (size_t)(r0 + 8) * N + c) =
                    make_float2(acc[m][j][2], acc[m][j][3]);
            }
        }
    } else {
        // fused RoPE + bf16 hi/lo split; CTA's n-range lies entirely in Q, K, or V.
        __nv_bfloat16 *oh, *ol;
        int ld, nbase;
        bool rope;
        if (n0 < DIM) { oh = qh; ol = ql; ld = DIM; nbase = 0; rope = true; }
        else if (n0 < DIM + KVD) { oh = kh; ol = kl; ld = KVD; nbase = DIM; rope = true; }
        else { oh = vh; ol = vl; ld = KVD; nbase = DIM + KVD; rope = false; }
#pragma unroll
        for (int m = 0; m < 4; m++) {
            int r0 = m0 + wm + m * 16 + (lane >> 2);
#pragma unroll
            for (int j = 0; j < 8; j++) {
                int c = n0 + wn + j * 8 + (lane & 3) * 2;
                float a0 = acc[m][j][0], a1 = acc[m][j][1];   // row r0
                float b0 = acc[m][j][2], b1 = acc[m][j][3];   // row r0+8
                if (rope) {
                    int i = (c & 127) >> 1;
                    float c0 = cs[r0 * 64 + i], s0 = sn[r0 * 64 + i];
                    float c1 = cs[(r0 + 8) * 64 + i], s1 = sn[(r0 + 8) * 64 + i];
                    float t0 = a0 * c0 - a1 * s0, t1 = a0 * s0 + a1 * c0;
                    a0 = t0; a1 = t1;
                    t0 = b0 * c1 - b1 * s1; t1 = b0 * s1 + b1 * c1;
                    b0 = t0; b1 = t1;
                }
                int cl = c - nbase;
                unsigned hA = pack_bf2(a0, a1);
                unsigned lA = pack_bf2(a0 - bf2lo(hA), a1 - bf2hi(hA));
                unsigned hB = pack_bf2(b0, b1);
                unsigned lB = pack_bf2(b0 - bf2lo(hB), b1 - bf2hi(hB));
                *(unsigned*)(oh + (size_t)r0 * ld + cl) = hA;
                *(unsigned*)(ol + (size_t)r0 * ld + cl) = lA;
                *(unsigned*)(oh + (size_t)(r0 + 8) * ld + cl) = hB;
                *(unsigned*)(ol + (size_t)(r0 + 8) * ld + cl) = lB;
            }
        }
    }
}

// ---------------- tensorized flash attention: 64-row q tiles, 2 CTAs/SM ----------
// 4 warps/CTA (warp owns 16 q-rows, math identical to prior version).
// Single KV buffer; intra-CTA load exposure hidden by the co-resident CTA.
#define AQ 64
#define AKV 64
#define LDA 136
#define QARR (64 * LDA * 2)               // 17408 B
#define KARR (64 * LDA * 2)               // 17408 B
#define SMEM_ATT (2 * QARR + 4 * KARR)    // 104448 B -> 2 CTAs/SM

__global__ __launch_bounds__(128, 2)
void attn_mma(const __nv_bfloat16* __restrict__ Qh, const __nv_bfloat16* __restrict__ Ql,
              const __nv_bfloat16* __restrict__ Kh, const __nv_bfloat16* __restrict__ Kl,
              const __nv_bfloat16* __restrict__ Vh, const __nv_bfloat16* __restrict__ Vl,
              __nv_bfloat16* __restrict__ Oh, __nv_bfloat16* __restrict__ Ol) {
    extern __shared__ char smem[];
    const uint32_t sb = smem_u32(smem);
    const int tid = threadIdx.x;
    const int lane = tid & 31, warp = tid >> 5;
    const int h = blockIdx.y;
    const int qt = (gridDim.x - 1) - blockIdx.x;   // long tiles first
    const int q0 = qt * AQ;
    const int kvh = h >> 2;
    const float scale = 0.08838834764831845f;
    const float NEGF = -1e30f;

    const uint32_t kb = sb + 2 * QARR;       // single KV buffer
    const uint32_t vb = kb + 2 * KARR;

    // Q tile load (64 rows x 256B, hi+lo)
#pragma unroll
    for (int s = tid; s < 64 * 16; s += 128) {
        int row = s >> 4, c = s & 15;
        uint32_t so = sb + (uint32_t)row * (LDA * 2) + c * 16;
        size_t go = (size_t)(q0 + row) * DIM + h * HD + c * 8;
        cpa16(so, Qh + go);
        cpa16(so + QARR, Ql + go);
    }
    auto load_kv = [&](int k0) {
#pragma unroll
        for (int s = tid; s < 1024; s += 128) {
            int row = s >> 4, c = s & 15;
            uint32_t so = (uint32_t)row * (LDA * 2) + c * 16;
            size_t go = (size_t)(k0 + row) * KVD + kvh * HD + c * 8;
            cpa16(kb + so, Kh + go);
            cpa16(kb + KARR + so, Kl + go);
            cpa16(vb + so, Vh + go);
            cpa16(vb + KARR + so, Vl + go);
        }
        asm volatile("cp.async.commit_group;");
    };
    load_kv(0);

    const int rA = q0 + warp * 16 + (lane >> 2);
    float mA = NEGF, mB = NEGF, lA = 0.f, lB = 0.f;
    float o[16][4];
#pragma unroll
    for (int j = 0; j < 16; j++)
#pragma unroll
        for (int v = 0; v < 4; v++) o[j][v] = 0.f;

    const int ntiles = qt + 1;
#pragma unroll 1
    for (int t = 0; t < ntiles; t++) {
        const int k0 = t * AKV;
        asm volatile("cp.async.wait_group 0;");
        __syncthreads();   // KV(t) (and Q on t=0) visible to all warps

        {
            float s[8][4];
#pragma unroll
            for (int j = 0; j < 8; j++)
#pragma unroll
                for (int v = 0; v < 4; v++) s[j][v] = 0.f;

            // S = Q K^T; K fragments via x4 (two j-subtiles per ldmatrix)
#pragma unroll
            for (int kc = 0; kc < 8; kc++) {
                uint32_t qa = sb + (uint32_t)(warp * 16 + (lane & 15)) * (LDA * 2) +
                              (uint32_t)(kc * 16 + (lane >> 4) * 8) * 2;
                unsigned aqh[4], aql[4];
                ldsm4(aqh, qa);
                ldsm4(aql, qa + QARR);
#pragma unroll
                for (int jj = 0; jj < 4; jj++) {
                    uint32_t ka = kb +
                        (uint32_t)(jj * 16 + ((lane >> 4) & 1) * 8 + (lane & 7)) * (LDA * 2) +
                        (uint32_t)(kc * 16 + ((lane >> 3) & 1) * 8) * 2;
                    unsigned bkh[4], bkl[4];
                    ldsm4(bkh, ka);
                    ldsm4(bkl, ka + KARR);
                    mma16816(s[2 * jj], aqh, bkh);
                    mma16816(s[2 * jj], aqh, bkl);
                    mma16816(s[2 * jj], aql, bkh);
                    mma16816(s[2 * jj + 1], aqh, bkh + 2);
                    mma16816(s[2 * jj + 1], aqh, bkl + 2);
                    mma16816(s[2 * jj + 1], aql, bkh + 2);
                }
            }

            const bool need_mask = (k0 + AKV - 1) > (q0 + warp * 16);
#pragma unroll
            for (int j = 0; j < 8; j++) {
#pragma unroll
                for (int v = 0; v < 4; v++) s[j][v] *= scale;
                if (need_mask) {
                    int cg = k0 + j * 8 + (lane & 3) * 2;
                    if (cg > rA) s[j][0] = NEGF;
                    if (cg + 1 > rA) s[j][1] = NEGF;
                    if (cg > rA + 8) s[j][2] = NEGF;
                    if (cg + 1 > rA + 8) s[j][3] = NEGF;
                }
            }

            float mxA = NEGF, mxB = NEGF;
#pragma unroll
            for (int j = 0; j < 8; j++) {
                mxA = fmaxf(mxA, fmaxf(s[j][0], s[j][1]));
                mxB = fmaxf(mxB, fmaxf(s[j][2], s[j][3]));
            }
            mxA = fmaxf(mxA, __shfl_xor_sync(0xffffffffu, mxA, 1));
            mxA = fmaxf(mxA, __shfl_xor_sync(0xffffffffu, mxA, 2));
            mxB = fmaxf(mxB, __shfl_xor_sync(0xffffffffu, mxB, 1));
            mxB = fmaxf(mxB, __shfl_xor_sync(0xffffffffu, mxB, 2));
            float mAn = fmaxf(mA, mxA), mBn = fmaxf(mB, mxB);
            float fA = __expf(mA - mAn), fB = __expf(mB - mBn);
            float sA = 0.f, sB = 0.f;
#pragma unroll
            for (int j = 0; j < 8; j++) {
                s[j][0] = __expf(s[j][0] - mAn);
                s[j][1] = __expf(s[j][1] - mAn);
                s[j][2] = __expf(s[j][2] - mBn);
                s[j][3] = __expf(s[j][3] - mBn);
                sA += s[j][0] + s[j][1];
                sB += s[j][2] + s[j][3];
            }
            sA += __shfl_xor_sync(0xffffffffu, sA, 1);
            sA += __shfl_xor_sync(0xffffffffu, sA, 2);
            sB += __shfl_xor_sync(0xffffffffu, sB, 1);
            sB += __shfl_xor_sync(0xffffffffu, sB, 2);
            lA = lA * fA + sA;
            lB = lB * fB + sB;
            mA = mAn;
            mB = mBn;
#pragma unroll
            for (int j = 0; j < 16; j++) {
                o[j][0] *= fA;
                o[j][1] *= fA;
                o[j][2] *= fB;
                o[j][3] *= fB;
            }

            // O += P V; V^T fragments via x4 trans
#pragma unroll
            for (int kc = 0; kc < 4; kc++) {
                const int j0 = 2 * kc, j1 = 2 * kc + 1;
                unsigned ph[4], pl[4];
                ph[0] = pack_bf2(s[j0][0], s[j0][1]);
                ph[1] = pack_bf2(s[j0][2], s[j0][3]);
                ph[2] = pack_bf2(s[j1][0], s[j1][1]);
                ph[3] = pack_bf2(s[j1][2], s[j1][3]);
                pl[0] = pack_bf2(s[j0][0] - bf2lo(ph[0]), s[j0][1] - bf2hi(ph[0]));
                pl[1] = pack_bf2(s[j0][2] - bf2lo(ph[1]), s[j0][3] - bf2hi(ph[1]));
                pl[2] = pack_bf2(s[j1][0] - bf2lo(ph[2]), s[j1][1] - bf2hi(ph[2]));
                pl[3] = pack_bf2(s[j1][2] - bf2lo(ph[3]), s[j1][3] - bf2hi(ph[3]));
#pragma unroll
                for (int jj = 0; jj < 8; jj++) {
                    uint32_t va = vb +
                        (uint32_t)(kc * 16 + (lane & 15)) * (LDA * 2) +
                        (uint32_t)((2 * jj + (lane >> 4)) * 8) * 2;
                    unsigned bvh[4], bvl[4];
                    ldsm4t(bvh, va);
                    ldsm4t(bvl, va + KARR);
                    mma16816(o[2 * jj], ph, bvh);
                    mma16816(o[2 * jj], ph, bvl);
                    mma16816(o[2 * jj], pl, bvh);
                    mma16816(o[2 * jj + 1], ph, bvh + 2);
                    mma16816(o[2 * jj + 1], ph, bvl + 2);
                    mma16816(o[2 * jj + 1], pl, bvh + 2);
                }
            }
        }

        __syncthreads();   // all warps done reading the KV buffer
        if (t + 1 < ntiles) load_kv((t + 1) * AKV);
    }

    float rlA = 1.0f / lA, rlB = 1.0f / lB;
#pragma unroll
    for (int j = 0; j < 16; j++) {
        int c = h * HD + j * 8 + (lane & 3) * 2;
        float a0 = o[j][0] * rlA, a1 = o[j][1] * rlA;
        float b0 = o[j][2] * rlB, b1 = o[j][3] * rlB;
        unsigned hA = pack_bf2(a0, a1);
        unsigned lAp = pack_bf2(a0 - bf2lo(hA), a1 - bf2hi(hA));
        unsigned hB = pack_bf2(b0, b1);
        unsigned lBp = pack_bf2(b0 - bf2lo(hB), b1 - bf2hi(hB));
        *(unsigned*)(Oh + (size_t)rA * DIM + c) = hA;
        *(unsigned*)(Ol + (size_t)rA * DIM + c) = lAp;
        *(unsigned*)(Oh + (size_t)(rA + 8) * DIM + c) = hB;
        *(unsigned*)(Ol + (size_t)(rA + 8) * DIM + c) = lBp;
    }
}

// ---------------- launch --------------------------------------------------------
extern "C" void kernel_launch(void* const* d_in, const int* in_sizes, int n_in,
                              void* d_out, int out_size) {
    const float* x  = (const float*)d_in[0];
    const float* wq = (const float*)d_in[1];
    const float* wk = (const float*)d_in[2];
    const float* wv = (const float*)d_in[3];
    const float* wo = (const float*)d_in[4];
    const float* fc = (const float*)d_in[5];
    const float* fs = (const float*)d_in[6];
    float* out = (float*)d_out;

    __nv_bfloat16 *xh, *xl, *ah, *al, *qh, *ql, *kh, *kl, *vh, *vl, *wh, *wl, *woh, *wol;
    cudaGetSymbolAddress((void**)&xh, g_xh);
    cudaGetSymbolAddress((void**)&xl, g_xl);
    cudaGetSymbolAddress((void**)&ah, g_ah);
    cudaGetSymbolAddress((void**)&al, g_al);
    cudaGetSymbolAddress((void**)&qh, g_qh);
    cudaGetSymbolAddress((void**)&ql, g_ql);
    cudaGetSymbolAddress((void**)&kh, g_kh);
    cudaGetSymbolAddress((void**)&kl, g_kl);
    cudaGetSymbolAddress((void**)&vh, g_vh);
    cudaGetSymbolAddress((void**)&vl, g_vl);
    cudaGetSymbolAddress((void**)&wh, g_wh);
    cudaGetSymbolAddress((void**)&wl, g_wl);
    cudaGetSymbolAddress((void**)&woh, g_woh);
    cudaGetSymbolAddress((void**)&wol, g_wol);

    dim3 tsb(32, 8);
    transpose_split_qkv<<<dim3(NQKV / 32, DIM / 32), tsb>>>(wq, wk, wv, wh, wl);
    transpose_split<<<dim3(DIM / 32, DIM / 32), tsb>>>(wo, woh, wol, DIM, DIM);
    split_kernel<<<(SEQ * DIM + 255) / 256, 256>>>(x, xh, xl, SEQ * DIM);

    cudaFuncSetAttribute(gemm_hmma<0>, cudaFuncAttributeMaxDynamicSharedMemorySize, SMEM_GEMM);
    cudaFuncSetAttribute(gemm_hmma<1>, cudaFuncAttributeMaxDynamicSharedMemorySize, SMEM_GEMM);

    // QKV projection with fused RoPE + split epilogue (compile-time MODE 1)
    gemm_hmma<1><<<dim3(NQKV / BN, SEQ / BM), 128, SMEM_GEMM>>>(
        xh, xl, wh, wl, nullptr, fc, fs, qh, ql, kh, kl, vh, vl, SEQ, NQKV, DIM);

    cudaFuncSetAttribute(attn_mma, cudaFuncAttributeMaxDynamicSharedMemorySize, SMEM_ATT);
    attn_mma<<<dim3(SEQ / AQ, NH), 128, SMEM_ATT>>>(qh, ql, kh, kl, vh, vl, ah, al);

    // output projection (compile-time MODE 0, fp32 out)
    gemm_hmma<0><<<dim3(DIM / BN, SEQ / BM), 128, SMEM_GEMM>>>(
        ah, al, woh, wol, out, nullptr, nullptr,
        nullptr, nullptr, nullptr, nullptr, nullptr, nullptr, SEQ, DIM, DIM);
}

// round 15
// speedup vs baseline: 1.1958x; 1.0034x over previous
#include <cuda_runtime.h>
#include <cuda_bf16.h>
#include <cstdint>

#define SEQ 2048
#define DIM 4096
#define NH 32
#define NKV 8
#define HD 128
#define KVD 1024   // NKV*HD
#define NQKV 6144  // DIM + 2*KVD

// ---------------- scratch (device globals) ----------------
__device__ __align__(128) __nv_bfloat16 g_xh[SEQ * DIM];
__device__ __align__(128) __nv_bfloat16 g_xl[SEQ * DIM];
__device__ __align__(128) __nv_bfloat16 g_ah[SEQ * DIM];
__device__ __align__(128) __nv_bfloat16 g_al[SEQ * DIM];
__device__ __align__(128) __nv_bfloat16 g_qh[SEQ * DIM];
__device__ __align__(128) __nv_bfloat16 g_ql[SEQ * DIM];
__device__ __align__(128) __nv_bfloat16 g_kh[SEQ * KVD];
__device__ __align__(128) __nv_bfloat16 g_kl[SEQ * KVD];
__device__ __align__(128) __nv_bfloat16 g_vh[SEQ * KVD];
__device__ __align__(128) __nv_bfloat16 g_vl[SEQ * KVD];
__device__ __align__(128) __nv_bfloat16 g_wh[NQKV * DIM];
__device__ __align__(128) __nv_bfloat16 g_wl[NQKV * DIM];
__device__ __align__(128) __nv_bfloat16 g_woh[DIM * DIM];
__device__ __align__(128) __nv_bfloat16 g_wol[DIM * DIM];

// ---------------- PTX helpers (baseline-PTX, sm_80-class) ----------------
__device__ __forceinline__ uint32_t smem_u32(const void* p) {
    uint32_t a;
    asm("{ .reg .u64 t; cvta.to.shared.u64 t, %1; cvt.u32.u64 %0, t; }" : "=r"(a) : "l"(p));
    return a;
}
__device__ __forceinline__ void cpa16(uint32_t s, const void* g) {
    asm volatile("cp.async.cg.shared.global [%0], [%1], 16;" :: "r"(s), "l"(g));
}
__device__ __forceinline__ void ldsm4(unsigned* r, uint32_t addr) {
    asm volatile("ldmatrix.sync.aligned.m8n8.x4.shared.b16 {%0,%1,%2,%3}, [%4];"
                 : "=r"(r[0]), "=r"(r[1]), "=r"(r[2]), "=r"(r[3]) : "r"(addr));
}
__device__ __forceinline__ void ldsm2(unsigned* r, uint32_t addr) {
    asm volatile("ldmatrix.sync.aligned.m8n8.x2.shared.b16 {%0,%1}, [%2];"
                 : "=r"(r[0]), "=r"(r[1]) : "r"(addr));
}
__device__ __forceinline__ void ldsm4t(unsigned* r, uint32_t addr) {
    asm volatile("ldmatrix.sync.aligned.m8n8.x4.trans.shared.b16 {%0,%1,%2,%3}, [%4];"
                 : "=r"(r[0]), "=r"(r[1]), "=r"(r[2]), "=r"(r[3]) : "r"(addr));
}
__device__ __forceinline__ void mma16816(float* d, const unsigned* a, const unsigned* b) {
    asm volatile(
        "mma.sync.aligned.m16n8k16.row.col.f32.bf16.bf16.f32 "
        "{%0,%1,%2,%3}, {%4,%5,%6,%7}, {%8,%9}, {%0,%1,%2,%3};"
        : "+f"(d[0]), "+f"(d[1]), "+f"(d[2]), "+f"(d[3])
        : "r"(a[0]), "r"(a[1]), "r"(a[2]), "r"(a[3]), "r"(b[0]), "r"(b[1]));
}
__device__ __forceinline__ unsigned pack_bf2(float lo, float hi) {
    unsigned d;
    asm("cvt.rn.bf16x2.f32 %0, %1, %2;" : "=r"(d) : "f"(hi), "f"(lo));
    return d;
}
__device__ __forceinline__ float bf2lo(unsigned r) { return __uint_as_float(r << 16); }
__device__ __forceinline__ float bf2hi(unsigned r) { return __uint_as_float(r & 0xffff0000u); }

// ---------------- conversion kernels ----------------
__global__ void split_kernel(const float* __restrict__ x, __nv_bfloat16* __restrict__ h,
                             __nv_bfloat16* __restrict__ l, int n) {
    int i = blockIdx.x * blockDim.x + threadIdx.x;
    if (i >= n) return;
    float v = x[i];
    __nv_bfloat16 hi = __float2bfloat16(v);
    __nv_bfloat16 lo = __float2bfloat16(v - __bfloat162float(hi));
    h[i] = hi;
    l[i] = lo;
}

__global__ void transpose_split_qkv(const float* __restrict__ wq, const float* __restrict__ wk,
                                    const float* __restrict__ wv,
                                    __nv_bfloat16* __restrict__ th, __nv_bfloat16* __restrict__ tl) {
    __shared__ float tile[32][33];
    int k0 = blockIdx.y * 32, n0 = blockIdx.x * 32;
    int tx = threadIdx.x, ty = threadIdx.y;   // 32 x 8
    const float* src;
    int nn0, ldn;
    if (n0 < DIM) { src = wq; nn0 = n0; ldn = DIM; }
    else if (n0 < DIM + KVD) { src = wk; nn0 = n0 - DIM; ldn = KVD; }
    else { src = wv; nn0 = n0 - DIM - KVD; ldn = KVD; }
#pragma unroll
    for (int r = 0; r < 4; r++)
        tile[ty + r * 8][tx] = src[(size_t)(k0 + ty + r * 8) * ldn + nn0 + tx];
    __syncthreads();
#pragma unroll
    for (int r = 0; r < 4; r++) {
        float v = tile[tx][ty + r * 8];
        __nv_bfloat16 hi = __float2bfloat16(v);
        __nv_bfloat16 lo = __float2bfloat16(v - __bfloat162float(hi));
        size_t o = (size_t)(n0 + ty + r * 8) * DIM + k0 + tx;
        th[o] = hi;
        tl[o] = lo;
    }
}

__global__ void transpose_split(const float* __restrict__ w, __nv_bfloat16* __restrict__ th,
                                __nv_bfloat16* __restrict__ tl, int K, int N) {
    __shared__ float tile[32][33];
    int k0 = blockIdx.y * 32, n0 = blockIdx.x * 32;
    int tx = threadIdx.x, ty = threadIdx.y;
#pragma unroll
    for (int r = 0; r < 4; r++)
        tile[ty + r * 8][tx] = w[(size_t)(k0 + ty + r * 8) * N + n0 + tx];
    __syncthreads();
#pragma unroll
    for (int r = 0; r < 4; r++) {
        float v = tile[tx][ty + r * 8];
        __nv_bfloat16 hi = __float2bfloat16(v);
        __nv_bfloat16 lo = __float2bfloat16(v - __bfloat162float(hi));
        size_t o = (size_t)(n0 + ty + r * 8) * K + k0 + tx;
        th[o] = hi;
        tl[o] = lo;
    }
}

// ---------------- HMMA bf16x3 GEMM (R10 mainloop, FROZEN) ----------------
// MODE 1 epilogue folds scale*log2e into Q (base-2 softmax downstream).
#define BM 128
#define BN 128
#define BK 32
#define LDE 40                     // padded bf16/row (80B: conflict-free LDSM)
#define ARR (128 * LDE * 2)        // 10240 B
#define STG (4 * ARR)              // 40960 B per stage
#define SMEM_GEMM (2 * STG)        // 81920 B

#define QSC (0.08838834764831845f * 1.4426950408889634f)

template <int MODE>
__global__ __launch_bounds__(128, 2)
void gemm_hmma(const __nv_bfloat16* __restrict__ Ah, const __nv_bfloat16* __restrict__ Al,
               const __nv_bfloat16* __restrict__ Bh, const __nv_bfloat16* __restrict__ Bl,
               float* __restrict__ C,
               const float* __restrict__ cs, const float* __restrict__ sn,
               __nv_bfloat16* __restrict__ qh, __nv_bfloat16* __restrict__ ql,
               __nv_bfloat16* __restrict__ kh, __nv_bfloat16* __restrict__ kl,
               __nv_bfloat16* __restrict__ vh, __nv_bfloat16* __restrict__ vl,
               int M, int N, int K) {
    extern __shared__ char smem[];
    const uint32_t sb = smem_u32(smem);
    const int tid = threadIdx.x;
    const int lane = tid & 31, warp = tid >> 5;
    const int m0 = blockIdx.y * BM, n0 = blockIdx.x * BN;
    const int wm = (warp & 1) * 64, wn = (warp >> 1) * 64;

    float acc[4][8][4];
#pragma unroll
    for (int m = 0; m < 4; m++)
#pragma unroll
        for (int j = 0; j < 8; j++)
#pragma unroll
            for (int v = 0; v < 4; v++) acc[m][j][v] = 0.f;

    auto load_stage = [&](int buf, int ko) {
        uint32_t s0 = sb + buf * STG;
#pragma unroll
        for (int s = tid; s < 512; s += 128) {
            int row = s >> 2, c = s & 3;
            uint32_t so = s0 + (uint32_t)row * (LDE * 2) + c * 16;
            size_t go = (size_t)row * K + ko + c * 8;
            cpa16(so, Ah + (size_t)m0 * K + go);
            cpa16(so + ARR, Al + (size_t)m0 * K + go);
            cpa16(so + 2 * ARR, Bh + (size_t)n0 * K + go);
            cpa16(so + 3 * ARR, Bl + (size_t)n0 * K + go);
        }
        asm volatile("cp.async.commit_group;");
    };

    load_stage(0, 0);
    const int NS = K / BK;
#pragma unroll 1
    for (int s = 0; s < NS; s++) {
        if (s + 1 < NS) {
            load_stage((s + 1) & 1, (s + 1) * BK);
            asm volatile("cp.async.wait_group 1;");
        } else {
            asm volatile("cp.async.wait_group 0;");
        }
        __syncthreads();

        const uint32_t base = sb + (s & 1) * STG;
#pragma unroll
        for (int ks = 0; ks < 2; ks++) {
            const int k0 = ks * 16;
            unsigned ah[4][4], al[4][4];
#pragma unroll
            for (int m = 0; m < 4; m++) {
                uint32_t aa = base +
                    (uint32_t)(wm + m * 16 + (lane & 15)) * (LDE * 2) +
                    (uint32_t)(k0 + (lane >> 4) * 8) * 2;
                ldsm4(ah[m], aa);
                ldsm4(al[m], aa + ARR);
            }
#pragma unroll
            for (int j = 0; j < 8; j++) {
                uint32_t ba = base + 2 * ARR +
                    (uint32_t)(wn + j * 8 + (lane & 7)) * (LDE * 2) +
                    (uint32_t)(k0 + ((lane >> 3) & 1) * 8) * 2;
                unsigned bh[2], bl[2];
                ldsm2(bh, ba);
                ldsm2(bl, ba + ARR);
#pragma unroll
                for (int m = 0; m < 4; m++) {
                    mma16816(acc[m][j], ah[m], bh);
                    mma16816(acc[m][j], ah[m], bl);
                    mma16816(acc[m][j], al[m], bh);
                }
            }
        }
        __syncthreads();
    }

    if (MODE == 0) {
#pragma unroll
        for (int m = 0; m < 4; m++) {
            int r0 = m0 + wm + m * 16 + (lane >> 2);
#pragma unroll
            for (int j = 0; j < 8; j++) {
                int c = n0 + wn + j * 8 + (lane & 3) * 2;
                *(float2*)(C + (size_t)r0 * N + c) = make_float2(acc[m][j][0], acc[m][j][1]);
                *(float2*)(C + (size_t)(r0 + 8) * N + c) =
                    make_float2(acc[m][j][2], acc[m][j][3]);
            }
        }
    } else {
        // fused RoPE + bf16 hi/lo split; Q additionally scaled by scale*log2e.
        __nv_bfloat16 *oh, *ol;
        int ld, nbase;
        bool rope;
        float qsc;
        if (n0 < DIM) { oh = qh; ol = ql; ld = DIM; nbase = 0; rope = true; qsc = QSC; }
        else if (n0 < DIM + KVD) { oh = kh; ol = kl; ld = KVD; nbase = DIM; rope = true; qsc = 1.f; }
        else { oh = vh; ol = vl; ld = KVD; nbase = DIM + KVD; rope = false; qsc = 1.f; }
#pragma unroll
        for (int m = 0; m < 4; m++) {
            int r0 = m0 + wm + m * 16 + (lane >> 2);
#pragma unroll
            for (int j = 0; j < 8; j++) {
                int c = n0 + wn + j * 8 + (lane & 3) * 2;
                float a0 = acc[m][j][0], a1 = acc[m][j][1];   // row r0
                float b0 = acc[m][j][2], b1 = acc[m][j][3];   // row r0+8
                if (rope) {
                    int i = (c & 127) >> 1;
                    float c0 = cs[r0 * 64 + i], s0 = sn[r0 * 64 + i];
                    float c1 = cs[(r0 + 8) * 64 + i], s1 = sn[(r0 + 8) * 64 + i];
                    float t0 = (a0 * c0 - a1 * s0) * qsc, t1 = (a0 * s0 + a1 * c0) * qsc;
                    a0 = t0; a1 = t1;
                    t0 = (b0 * c1 - b1 * s1) * qsc; t1 = (b0 * s1 + b1 * c1) * qsc;
                    b0 = t0; b1 = t1;
                }
                int cl = c - nbase;
                unsigned hA = pack_bf2(a0, a1);
                unsigned lA = pack_bf2(a0 - bf2lo(hA), a1 - bf2hi(hA));
                unsigned hB = pack_bf2(b0, b1);
                unsigned lB = pack_bf2(b0 - bf2lo(hB), b1 - bf2hi(hB));
                *(unsigned*)(oh + (size_t)r0 * ld + cl) = hA;
                *(unsigned*)(ol + (size_t)r0 * ld + cl) = lA;
                *(unsigned*)(oh + (size_t)(r0 + 8) * ld + cl) = hB;
                *(unsigned*)(ol + (size_t)(r0 + 8) * ld + cl) = lB;
            }
        }
    }
}

// ---------------- tensorized flash attention: base-2 softmax, 2 CTAs/SM ----------
#define AQ 64
#define AKV 64
#define LDA 136
#define QARR (64 * LDA * 2)               // 17408 B
#define KARR (64 * LDA * 2)               // 17408 B
#define SMEM_ATT (2 * QARR + 4 * KARR)    // 104448 B -> 2 CTAs/SM

__global__ __launch_bounds__(128, 2)
void attn_mma(const __nv_bfloat16* __restrict__ Qh, const __nv_bfloat16* __restrict__ Ql,
              const __nv_bfloat16* __restrict__ Kh, const __nv_bfloat16* __restrict__ Kl,
              const __nv_bfloat16* __restrict__ Vh, const __nv_bfloat16* __restrict__ Vl,
              __nv_bfloat16* __restrict__ Oh, __nv_bfloat16* __restrict__ Ol) {
    extern __shared__ char smem[];
    const uint32_t sb = smem_u32(smem);
    const int tid = threadIdx.x;
    const int lane = tid & 31, warp = tid >> 5;
    const int h = blockIdx.y;
    const int qt = (gridDim.x - 1) - blockIdx.x;   // long tiles first
    const int q0 = qt * AQ;
    const int kvh = h >> 2;
    const float NEGF = -1e30f;

    const uint32_t kb = sb + 2 * QARR;       // single KV buffer
    const uint32_t vb = kb + 2 * KARR;

#pragma unroll
    for (int s = tid; s < 64 * 16; s += 128) {
        int row = s >> 4, c = s & 15;
        uint32_t so = sb + (uint32_t)row * (LDA * 2) + c * 16;
        size_t go = (size_t)(q0 + row) * DIM + h * HD + c * 8;
        cpa16(so, Qh + go);
        cpa16(so + QARR, Ql + go);
    }
    auto load_kv = [&](int k0) {
#pragma unroll
        for (int s = tid; s < 1024; s += 128) {
            int row = s >> 4, c = s & 15;
            uint32_t so = (uint32_t)row * (LDA * 2) + c * 16;
            size_t go = (size_t)(k0 + row) * KVD + kvh * HD + c * 8;
            cpa16(kb + so, Kh + go);
            cpa16(kb + KARR + so, Kl + go);
            cpa16(vb + so, Vh + go);
            cpa16(vb + KARR + so, Vl + go);
        }
        asm volatile("cp.async.commit_group;");
    };
    load_kv(0);

    const int rA = q0 + warp * 16 + (lane >> 2);
    float mA = NEGF, mB = NEGF, lA = 0.f, lB = 0.f;
    float o[16][4];
#pragma unroll
    for (int j = 0; j < 16; j++)
#pragma unroll
        for (int v = 0; v < 4; v++) o[j][v] = 0.f;

    const int ntiles = qt + 1;
#pragma unroll 1
    for (int t = 0; t < ntiles; t++) {
        const int k0 = t * AKV;
        asm volatile("cp.async.wait_group 0;");
        __syncthreads();

        {
            float s[8][4];
#pragma unroll
            for (int j = 0; j < 8; j++)
#pragma unroll
                for (int v = 0; v < 4; v++) s[j][v] = 0.f;

            // S = Q K^T (Q pre-scaled by scale*log2e)
#pragma unroll
            for (int kc = 0; kc < 8; kc++) {
                uint32_t qa = sb + (uint32_t)(warp * 16 + (lane & 15)) * (LDA * 2) +
                              (uint32_t)(kc * 16 + (lane >> 4) * 8) * 2;
                unsigned aqh[4], aql[4];
                ldsm4(aqh, qa);
                ldsm4(aql, qa + QARR);
#pragma unroll
                for (int jj = 0; jj < 4; jj++) {
                    uint32_t ka = kb +
                        (uint32_t)(jj * 16 + ((lane >> 4) & 1) * 8 + (lane & 7)) * (LDA * 2) +
                        (uint32_t)(kc * 16 + ((lane >> 3) & 1) * 8) * 2;
                    unsigned bkh[4], bkl[4];
                    ldsm4(bkh, ka);
                    ldsm4(bkl, ka + KARR);
                    mma16816(s[2 * jj], aqh, bkh);
                    mma16816(s[2 * jj], aqh, bkl);
                    mma16816(s[2 * jj], aql, bkh);
                    mma16816(s[2 * jj + 1], aqh, bkh + 2);
                    mma16816(s[2 * jj + 1], aqh, bkl + 2);
                    mma16816(s[2 * jj + 1], aql, bkh + 2);
                }
            }

            const bool need_mask = (k0 + AKV - 1) > (q0 + warp * 16);
            if (need_mask) {
#pragma unroll
                for (int j = 0; j < 8; j++) {
                    int cg = k0 + j * 8 + (lane & 3) * 2;
                    if (cg > rA) s[j][0] = NEGF;
                    if (cg + 1 > rA) s[j][1] = NEGF;
                    if (cg > rA + 8) s[j][2] = NEGF;
                    if (cg + 1 > rA + 8) s[j][3] = NEGF;
                }
            }

            float mxA = NEGF, mxB = NEGF;
#pragma unroll
            for (int j = 0; j < 8; j++) {
                mxA = fmaxf(mxA, fmaxf(s[j][0], s[j][1]));
                mxB = fmaxf(mxB, fmaxf(s[j][2], s[j][3]));
            }
            mxA = fmaxf(mxA, __shfl_xor_sync(0xffffffffu, mxA, 1));
            mxA = fmaxf(mxA, __shfl_xor_sync(0xffffffffu, mxA, 2));
            mxB = fmaxf(mxB, __shfl_xor_sync(0xffffffffu, mxB, 1));
            mxB = fmaxf(mxB, __shfl_xor_sync(0xffffffffu, mxB, 2));
            float mAn = fmaxf(mA, mxA), mBn = fmaxf(mB, mxB);
            float fA = exp2f(mA - mAn), fB = exp2f(mB - mBn);
            float sA = 0.f, sB = 0.f;
#pragma unroll
            for (int j = 0; j < 8; j++) {
                s[j][0] = exp2f(s[j][0] - mAn);
                s[j][1] = exp2f(s[j][1] - mAn);
                s[j][2] = exp2f(s[j][2] - mBn);
                s[j][3] = exp2f(s[j][3] - mBn);
                sA += s[j][0] + s[j][1];
                sB += s[j][2] + s[j][3];
            }
            sA += __shfl_xor_sync(0xffffffffu, sA, 1);
            sA += __shfl_xor_sync(0xffffffffu, sA, 2);
            sB += __shfl_xor_sync(0xffffffffu, sB, 1);
            sB += __shfl_xor_sync(0xffffffffu, sB, 2);
            lA = lA * fA + sA;
            lB = lB * fB + sB;
            mA = mAn;
            mB = mBn;
#pragma unroll
            for (int j = 0; j < 16; j++) {
                o[j][0] *= fA;
                o[j][1] *= fA;
                o[j][2] *= fB;
                o[j][3] *= fB;
            }

            // O += P V
#pragma unroll
            for (int kc = 0; kc < 4; kc++) {
                const int j0 = 2 * kc, j1 = 2 * kc + 1;
                unsigned ph[4], pl[4];
                ph[0] = pack_bf2(s[j0][0], s[j0][1]);
                ph[1] = pack_bf2(s[j0][2], s[j0][3]);
                ph[2] = pack_bf2(s[j1][0], s[j1][1]);
                ph[3] = pack_bf2(s[j1][2], s[j1][3]);
                pl[0] = pack_bf2(s[j0][0] - bf2lo(ph[0]), s[j0][1] - bf2hi(ph[0]));
                pl[1] = pack_bf2(s[j0][2] - bf2lo(ph[1]), s[j0][3] - bf2hi(ph[1]));
                pl[2] = pack_bf2(s[j1][0] - bf2lo(ph[2]), s[j1][1] - bf2hi(ph[2]));
                pl[3] = pack_bf2(s[j1][2] - bf2lo(ph[3]), s[j1][3] - bf2hi(ph[3]));
#pragma unroll
                for (int jj = 0; jj < 8; jj++) {
                    uint32_t va = vb +
                        (uint32_t)(kc * 16 + (lane & 15)) * (LDA * 2) +
                        (uint32_t)((2 * jj + (lane >> 4)) * 8) * 2;
                    unsigned bvh[4], bvl[4];
                    ldsm4t(bvh, va);
                    ldsm4t(bvl, va + KARR);
                    mma16816(o[2 * jj], ph, bvh);
                    mma16816(o[2 * jj], ph, bvl);
                    mma16816(o[2 * jj], pl, bvh);
                    mma16816(o[2 * jj + 1], ph, bvh + 2);
                    mma16816(o[2 * jj + 1], ph, bvl + 2);
                    mma16816(o[2 * jj + 1], pl, bvh + 2);
                }
            }
        }

        __syncthreads();
        if (t + 1 < ntiles) load_kv((t + 1) * AKV);
    }

    float rlA = 1.0f / lA, rlB = 1.0f / lB;
#pragma unroll
    for (int j = 0; j < 16; j++) {
        int c = h * HD + j * 8 + (lane & 3) * 2;
        float a0 = o[j][0] * rlA, a1 = o[j][1] * rlA;
        float b0 = o[j][2] * rlB, b1 = o[j][3] * rlB;
        unsigned hA = pack_bf2(a0, a1);
        unsigned lAp = pack_bf2(a0 - bf2lo(hA), a1 - bf2hi(hA));
        unsigned hB = pack_bf2(b0, b1);
        unsigned lBp = pack_bf2(b0 - bf2lo(hB), b1 - bf2hi(hB));
        *(unsigned*)(Oh + (size_t)rA * DIM + c) = hA;
        *(unsigned*)(Ol + (size_t)rA * DIM + c) = lAp;
        *(unsigned*)(Oh + (size_t)(rA + 8) * DIM + c) = hB;
        *(unsigned*)(Ol + (size_t)(rA + 8) * DIM + c) = lBp;
    }
}

// ---------------- launch --------------------------------------------------------
extern "C" void kernel_launch(void* const* d_in, const int* in_sizes, int n_in,
                              void* d_out, int out_size) {
    const float* x  = (const float*)d_in[0];
    const float* wq = (const float*)d_in[1];
    const float* wk = (const float*)d_in[2];
    const float* wv = (const float*)d_in[3];
    const float* wo = (const float*)d_in[4];
    const float* fc = (const float*)d_in[5];
    const float* fs = (const float*)d_in[6];
    float* out = (float*)d_out;

    __nv_bfloat16 *xh, *xl, *ah, *al, *qh, *ql, *kh, *kl, *vh, *vl, *wh, *wl, *woh, *wol;
    cudaGetSymbolAddress((void**)&xh, g_xh);
    cudaGetSymbolAddress((void**)&xl, g_xl);
    cudaGetSymbolAddress((void**)&ah, g_ah);
    cudaGetSymbolAddress((void**)&al, g_al);
    cudaGetSymbolAddress((void**)&qh, g_qh);
    cudaGetSymbolAddress((void**)&ql, g_ql);
    cudaGetSymbolAddress((void**)&kh, g_kh);
    cudaGetSymbolAddress((void**)&kl, g_kl);
    cudaGetSymbolAddress((void**)&vh, g_vh);
    cudaGetSymbolAddress((void**)&vl, g_vl);
    cudaGetSymbolAddress((void**)&wh, g_wh);
    cudaGetSymbolAddress((void**)&wl, g_wl);
    cudaGetSymbolAddress((void**)&woh, g_woh);
    cudaGetSymbolAddress((void**)&wol, g_wol);

    // Streams/events created once (first call is the non-captured correctness run).
    static cudaStream_t s2 = nullptr, s3 = nullptr;
    static cudaEvent_t e0 = nullptr, e2 = nullptr, e3 = nullptr;
    if (!s2) {
        cudaStreamCreateWithFlags(&s2, cudaStreamNonBlocking);
        cudaStreamCreateWithFlags(&s3, cudaStreamNonBlocking);
        cudaEventCreateWithFlags(&e0, cudaEventDisableTiming);
        cudaEventCreateWithFlags(&e2, cudaEventDisableTiming);
        cudaEventCreateWithFlags(&e3, cudaEventDisableTiming);
    }

    cudaFuncSetAttribute(gemm_hmma<0>, cudaFuncAttributeMaxDynamicSharedMemorySize, SMEM_GEMM);
    cudaFuncSetAttribute(gemm_hmma<1>, cudaFuncAttributeMaxDynamicSharedMemorySize, SMEM_GEMM);
    cudaFuncSetAttribute(attn_mma, cudaFuncAttributeMaxDynamicSharedMemorySize, SMEM_ATT);

    dim3 tsb(32, 8);
    // fork: wo-transpose on s2 (joined before final GEMM), qkv-transpose on s3
    cudaEventRecord(e0, 0);
    cudaStreamWaitEvent(s2, e0, 0);
    cudaStreamWaitEvent(s3, e0, 0);
    transpose_split<<<dim3(DIM / 32, DIM / 32), tsb, 0, s2>>>(wo, woh, wol, DIM, DIM);
    cudaEventRecord(e2, s2);
    transpose_split_qkv<<<dim3(NQKV / 32, DIM / 32), tsb, 0, s3>>>(wq, wk, wv, wh, wl);
    cudaEventRecord(e3, s3);
    split_kernel<<<(SEQ * DIM + 255) / 256, 256>>>(x, xh, xl, SEQ * DIM);
    cudaStreamWaitEvent(0, e3, 0);   // join qkv weights before QKV GEMM

    // QKV projection: fused RoPE + scale*log2e on Q + bf16 split (MODE 1)
    gemm_hmma<1><<<dim3(NQKV / BN, SEQ / BM), 128, SMEM_GEMM>>>(
        xh, xl, wh, wl, nullptr, fc, fs, qh, ql, kh, kl, vh, vl, SEQ, NQKV, DIM);

    attn_mma<<<dim3(SEQ / AQ, NH), 128, SMEM_ATT>>>(qh, ql, kh, kl, vh, vl, ah, al);

    cudaStreamWaitEvent(0, e2, 0);   // join wo weights before output GEMM
    gemm_hmma<0><<<dim3(DIM / BN, SEQ / BM), 128, SMEM_GEMM>>>(
        ah, al, woh, wol, out, nullptr, nullptr,
        nullptr, nullptr, nullptr, nullptr, nullptr, nullptr, SEQ, DIM, DIM);
}